// round 1
// baseline (speedup 1.0000x reference)
#include <cuda_runtime.h>
#include <cstddef>

#define Bb 256
#define Tt 512
#define Ii 64
#define Hh 512
#define Gg 2048   // 4*H

// ---------------- static device scratch (allowed; no runtime allocs) ------
__device__ float g_xg[(size_t)Bb * Tt * Gg];     // 1.0 GiB gate pre-activations
__device__ float g_hseq[(size_t)Bb * Tt * Hh];   // 256 MiB layer-0 hidden seq
__device__ float g_hbuf[2 * (size_t)Bb * Hh];    // double-buffered h
__device__ unsigned int g_bar_count;             // grid barrier counter

// ---------------- init: zero h buffers, reset barrier ---------------------
__global__ void init_kernel() {
    unsigned idx = blockIdx.x * blockDim.x + threadIdx.x;
    if (idx < 2u * Bb * Hh) g_hbuf[idx] = 0.f;
    if (idx == 0) g_bar_count = 0u;
}

// ---------------- GEMM: C[M,N] = A[M,K] @ W[N,K]^T + b1 + b2 --------------
// M = 131072 (grid.y*128), N = 2048 (grid.x*128). 128x128 tile, 8x8/thread.
__global__ void __launch_bounds__(256)
gemm_bias(const float* __restrict__ A, const float* __restrict__ W,
          const float* __restrict__ b1, const float* __restrict__ b2,
          float* __restrict__ C, int K)
{
    __shared__ float sA[128 * 17];   // [m][k], padded
    __shared__ float sB[16 * 132];   // [k][n], padded

    const int tid = threadIdx.x;
    const int tx = tid & 15;         // n-group (8 cols)
    const int ty = tid >> 4;         // m-group (8 rows)
    const size_t n0 = (size_t)blockIdx.x * 128;
    const size_t m0 = (size_t)blockIdx.y * 128;

    float acc[8][8];
#pragma unroll
    for (int i = 0; i < 8; ++i)
#pragma unroll
        for (int j = 0; j < 8; ++j) acc[i][j] = 0.f;

    for (int kk = 0; kk < K; kk += 16) {
#pragma unroll
        for (int i = 0; i < 2; ++i) {
            int idx = tid + i * 256;
            int row = idx >> 2;
            int kq = (idx & 3) * 4;
            float4 v = *reinterpret_cast<const float4*>(&A[(m0 + row) * (size_t)K + kk + kq]);
            sA[row * 17 + kq + 0] = v.x;
            sA[row * 17 + kq + 1] = v.y;
            sA[row * 17 + kq + 2] = v.z;
            sA[row * 17 + kq + 3] = v.w;
        }
#pragma unroll
        for (int i = 0; i < 2; ++i) {
            int idx = tid + i * 256;
            int row = idx >> 2;
            int kq = (idx & 3) * 4;
            float4 v = *reinterpret_cast<const float4*>(&W[(n0 + row) * (size_t)K + kk + kq]);
            sB[(kq + 0) * 132 + row] = v.x;
            sB[(kq + 1) * 132 + row] = v.y;
            sB[(kq + 2) * 132 + row] = v.z;
            sB[(kq + 3) * 132 + row] = v.w;
        }
        __syncthreads();
#pragma unroll
        for (int k = 0; k < 16; ++k) {
            float a[8], bb[8];
#pragma unroll
            for (int i = 0; i < 8; ++i) a[i] = sA[(ty * 8 + i) * 17 + k];
            float4 u0 = *reinterpret_cast<const float4*>(&sB[k * 132 + tx * 8]);
            float4 u1 = *reinterpret_cast<const float4*>(&sB[k * 132 + tx * 8 + 4]);
            bb[0] = u0.x; bb[1] = u0.y; bb[2] = u0.z; bb[3] = u0.w;
            bb[4] = u1.x; bb[5] = u1.y; bb[6] = u1.z; bb[7] = u1.w;
#pragma unroll
            for (int i = 0; i < 8; ++i)
#pragma unroll
                for (int j = 0; j < 8; ++j)
                    acc[i][j] = fmaf(a[i], bb[j], acc[i][j]);
        }
        __syncthreads();
    }

    float bias[8];
#pragma unroll
    for (int j = 0; j < 8; ++j) {
        size_t n = n0 + tx * 8 + j;
        bias[j] = b1[n] + b2[n];
    }
#pragma unroll
    for (int i = 0; i < 8; ++i) {
        size_t m = m0 + ty * 8 + i;
        float* cp = &C[m * Gg + n0 + tx * 8];
        float4 o0, o1;
        o0.x = acc[i][0] + bias[0]; o0.y = acc[i][1] + bias[1];
        o0.z = acc[i][2] + bias[2]; o0.w = acc[i][3] + bias[3];
        o1.x = acc[i][4] + bias[4]; o1.y = acc[i][5] + bias[5];
        o1.z = acc[i][6] + bias[6]; o1.w = acc[i][7] + bias[7];
        *reinterpret_cast<float4*>(cp) = o0;
        *reinterpret_cast<float4*>(cp + 4) = o1;
    }
}

// ---------------- persistent LSTM recurrence -------------------------------
// Grid: 128 CTAs = 4 M-tiles (64 batch rows) x 32 col-tiles (16 h-cols).
// Each CTA: 64 gate-columns = its 16 h-cols x 4 gates (i,f,g,o), so the cell
// update is CTA-local. W_hh slice (64 rows x 512) resident in SMEM. Cell
// state c lives in registers across all 512 steps. One grid barrier / step.
#define NCTA_R 128
#define KC 32
#define WPITCH 514   // 512 + 2 -> conflict-free column reads
#define HPITCH 36    // 32 + 4  -> 16B-aligned rows, conflict-free

#define SMEM_REC_BYTES ((64 * WPITCH + 2 * 64 * HPITCH) * 4)

__device__ __forceinline__ float sigmoidf_(float x) {
    return 1.0f / (1.0f + __expf(-x));
}

__global__ void __launch_bounds__(256, 1)
lstm_rec(const float* __restrict__ W_hh, const float* __restrict__ xg,
         float* __restrict__ hseq)
{
    extern __shared__ float smem[];
    float* sW = smem;                          // 64 x WPITCH
    float* sH = smem + 64 * WPITCH;            // 2 x 64 x HPITCH

    const int tid = threadIdx.x;
    const int mc = tid & 15;                   // h-col within CTA
    const int mr = tid >> 4;                   // row group (4 rows each)
    const int ctaM = blockIdx.x & 3;
    const int ctaC = blockIdx.x >> 2;
    const int m0 = ctaM * 64;
    const int hc0 = ctaC * 16;
    const int hc = hc0 + mc;
    const int hrow = mr * 4;

    // Load W_hh slice: smem row (g*16+c) <- W_hh[g*H + hc0 + c][:]
    for (int idx = tid; idx < 64 * Hh; idx += 256) {
        int row = idx >> 9;
        int k = idx & 511;
        int g = row >> 4, c = row & 15;
        sW[row * WPITCH + k] = W_hh[((size_t)g * Hh + hc0 + c) * Hh + k];
    }
    __syncthreads();

    const float* wptr[4];
#pragma unroll
    for (int g = 0; g < 4; ++g) wptr[g] = sW + (g * 16 + mc) * WPITCH;

    float cstate[4] = {0.f, 0.f, 0.f, 0.f};
    unsigned phase = 0;

    for (int t = 0; t < Tt; ++t) {
        const float* hin = g_hbuf + (size_t)(t & 1) * Bb * Hh;
        float* hout = g_hbuf + (size_t)((t + 1) & 1) * Bb * Hh;

        // Issue xg loads early (consumed in epilogue)
        float xgv[4][4];
#pragma unroll
        for (int g = 0; g < 4; ++g)
#pragma unroll
            for (int r = 0; r < 4; ++r) {
                size_t brow = m0 + hrow + r;
                xgv[g][r] = __ldcg(&xg[(brow * Tt + t) * Gg + (size_t)g * Hh + hc]);
            }

        float acc[4][4];
#pragma unroll
        for (int g = 0; g < 4; ++g)
#pragma unroll
            for (int r = 0; r < 4; ++r) acc[g][r] = 0.f;

        // prologue: load h chunk 0 (L2-coherent reads: L1 may be stale)
        float4 pf[2];
#pragma unroll
        for (int i = 0; i < 2; ++i) {
            int idx = tid + i * 256;
            int row = idx >> 3;
            int kq = (idx & 7) * 4;
            pf[i] = __ldcg(reinterpret_cast<const float4*>(
                &hin[(size_t)(m0 + row) * Hh + kq]));
        }
        int buf = 0;
#pragma unroll
        for (int i = 0; i < 2; ++i) {
            int idx = tid + i * 256;
            int row = idx >> 3;
            int kq = (idx & 7) * 4;
            *reinterpret_cast<float4*>(&sH[buf * (64 * HPITCH) + row * HPITCH + kq]) = pf[i];
        }
        __syncthreads();

#pragma unroll 1
        for (int cc = 0; cc < Hh / KC; ++cc) {
            if (cc < Hh / KC - 1) {
#pragma unroll
                for (int i = 0; i < 2; ++i) {
                    int idx = tid + i * 256;
                    int row = idx >> 3;
                    int kq = (idx & 7) * 4;
                    pf[i] = __ldcg(reinterpret_cast<const float4*>(
                        &hin[(size_t)(m0 + row) * Hh + (cc + 1) * KC + kq]));
                }
            }
            const float* sHb = sH + buf * (64 * HPITCH) + hrow * HPITCH;
            const int kbase = cc * KC;
#pragma unroll
            for (int k = 0; k < KC; ++k) {
                float hv[4], wv[4];
#pragma unroll
                for (int r = 0; r < 4; ++r) hv[r] = sHb[r * HPITCH + k];
#pragma unroll
                for (int g = 0; g < 4; ++g) wv[g] = wptr[g][kbase + k];
#pragma unroll
                for (int g = 0; g < 4; ++g)
#pragma unroll
                    for (int r = 0; r < 4; ++r)
                        acc[g][r] = fmaf(wv[g], hv[r], acc[g][r]);
            }
            __syncthreads();
            if (cc < Hh / KC - 1) {
                buf ^= 1;
#pragma unroll
                for (int i = 0; i < 2; ++i) {
                    int idx = tid + i * 256;
                    int row = idx >> 3;
                    int kq = (idx & 7) * 4;
                    *reinterpret_cast<float4*>(
                        &sH[buf * (64 * HPITCH) + row * HPITCH + kq]) = pf[i];
                }
                __syncthreads();
            }
        }

        // epilogue: activations + cell update (c in registers) + h write
#pragma unroll
        for (int r = 0; r < 4; ++r) {
            size_t brow = m0 + hrow + r;
            float iv = sigmoidf_(acc[0][r] + xgv[0][r]);
            float fv = sigmoidf_(acc[1][r] + xgv[1][r]);
            float gv = tanhf(acc[2][r] + xgv[2][r]);
            float ov = sigmoidf_(acc[3][r] + xgv[3][r]);
            cstate[r] = fv * cstate[r] + iv * gv;
            float hv = ov * tanhf(cstate[r]);
            hout[brow * Hh + hc] = hv;
            if (hseq) hseq[(brow * Tt + t) * Hh + hc] = hv;
        }

        // software grid barrier (release: fence-before-arrive)
        __threadfence();
        __syncthreads();
        phase += NCTA_R;
        if (tid == 0) {
            atomicAdd(&g_bar_count, 1u);
            while (*(volatile unsigned int*)&g_bar_count < phase) {
                __nanosleep(64);
            }
        }
        __syncthreads();
        __threadfence();
    }
}

// ---------------- final FC: out[b] = h_last[b,:] . W_fc + b_fc -------------
__global__ void fc_kernel(const float* __restrict__ h, const float* __restrict__ Wfc,
                          const float* __restrict__ bfc, float* __restrict__ out)
{
    int b = blockIdx.x;
    int tid = threadIdx.x;
    float s = 0.f;
    for (int k = tid; k < Hh; k += 128)
        s += h[(size_t)b * Hh + k] * Wfc[k];
#pragma unroll
    for (int o = 16; o > 0; o >>= 1) s += __shfl_xor_sync(0xffffffffu, s, o);
    __shared__ float ws[4];
    if ((tid & 31) == 0) ws[tid >> 5] = s;
    __syncthreads();
    if (tid == 0) out[b] = ws[0] + ws[1] + ws[2] + ws[3] + bfc[0];
}

// ---------------- launch ----------------------------------------------------
extern "C" void kernel_launch(void* const* d_in, const int* in_sizes, int n_in,
                              void* d_out, int out_size)
{
    (void)in_sizes; (void)n_in; (void)out_size;
    const float* x     = (const float*)d_in[0];
    const float* W_ih0 = (const float*)d_in[1];
    const float* W_hh0 = (const float*)d_in[2];
    const float* b_ih0 = (const float*)d_in[3];
    const float* b_hh0 = (const float*)d_in[4];
    const float* W_ih1 = (const float*)d_in[5];
    const float* W_hh1 = (const float*)d_in[6];
    const float* b_ih1 = (const float*)d_in[7];
    const float* b_hh1 = (const float*)d_in[8];
    const float* W_fc  = (const float*)d_in[9];
    const float* b_fc  = (const float*)d_in[10];
    float* out = (float*)d_out;

    void *p_xg = nullptr, *p_hseq = nullptr, *p_hbuf = nullptr;
    cudaGetSymbolAddress(&p_xg, g_xg);
    cudaGetSymbolAddress(&p_hseq, g_hseq);
    cudaGetSymbolAddress(&p_hbuf, g_hbuf);

    cudaFuncSetAttribute(lstm_rec, cudaFuncAttributeMaxDynamicSharedMemorySize,
                         SMEM_REC_BYTES);

    dim3 ggrid(16, 1024);  // N tiles x M tiles (2048/128, 131072/128)

    // Layer 0
    gemm_bias<<<ggrid, 256>>>(x, W_ih0, b_ih0, b_hh0, (float*)p_xg, Ii);
    init_kernel<<<1024, 256>>>();
    lstm_rec<<<NCTA_R, 256, SMEM_REC_BYTES>>>(W_hh0, (const float*)p_xg, (float*)p_hseq);

    // Layer 1
    gemm_bias<<<ggrid, 256>>>((const float*)p_hseq, W_ih1, b_ih1, b_hh1, (float*)p_xg, Hh);
    init_kernel<<<1024, 256>>>();
    lstm_rec<<<NCTA_R, 256, SMEM_REC_BYTES>>>(W_hh1, (const float*)p_xg, nullptr);

    // Final FC (h_last ends in buffer 0 since T=512 is even)
    fc_kernel<<<Bb, 128>>>((const float*)p_hbuf, W_fc, b_fc, out);
}

// round 2
// speedup vs baseline: 1.0064x; 1.0064x over previous
#include <cuda_runtime.h>
#include <cstddef>

#define Bb 256
#define Tt 512
#define Ii 64
#define Hh 512
#define Gg 2048   // 4*H

typedef unsigned long long ull;

// ---------------- f32x2 packed-math helpers (Blackwell FFMA2) --------------
__device__ __forceinline__ ull pack2(float lo, float hi) {
    ull r; asm("mov.b64 %0, {%1, %2};" : "=l"(r) : "f"(lo), "f"(hi)); return r;
}
__device__ __forceinline__ ull ld2u(const float* p) {
    float2 v = *reinterpret_cast<const float2*>(p);
    return pack2(v.x, v.y);
}
__device__ __forceinline__ ull fma2(ull a, ull b, ull c) {
    ull d; asm("fma.rn.f32x2 %0, %1, %2, %3;" : "=l"(d) : "l"(a), "l"(b), "l"(c));
    return d;
}
__device__ __forceinline__ float2 unpack2(ull v) {
    float2 r; asm("mov.b64 {%0, %1}, %2;" : "=f"(r.x), "=f"(r.y) : "l"(v)); return r;
}

// ---------------- static device scratch (allowed; no runtime allocs) ------
__device__ float g_xg[(size_t)Bb * Tt * Gg];     // 1.0 GiB gate pre-activations
__device__ float g_hseq[(size_t)Bb * Tt * Hh];   // 256 MiB layer-0 hidden seq
__device__ float g_hbuf[2 * (size_t)Bb * Hh];    // double-buffered h
__device__ unsigned int g_bar_count;             // grid barrier counter

// ---------------- init: zero h buffers, reset barrier ---------------------
__global__ void init_kernel() {
    unsigned idx = blockIdx.x * blockDim.x + threadIdx.x;
    if (idx < 2u * Bb * Hh) g_hbuf[idx] = 0.f;
    if (idx == 0) g_bar_count = 0u;
}

// ---------------- GEMM: C[M,N] = A[M,K] @ W[N,K]^T + b1 + b2 --------------
// M = 131072 (grid.y*128), N = 2048 (grid.x*128). 128x128 tile, 8x8/thread.
// Inner product uses FFMA2 (f32x2) packed over n-pairs.
__global__ void __launch_bounds__(256)
gemm_bias(const float* __restrict__ A, const float* __restrict__ W,
          const float* __restrict__ b1, const float* __restrict__ b2,
          float* __restrict__ C, int K)
{
    __shared__ float sA[128 * 17];   // [m][k], padded
    __shared__ float sB[16 * 132];   // [k][n], padded

    const int tid = threadIdx.x;
    const int tx = tid & 15;         // n-group (8 cols)
    const int ty = tid >> 4;         // m-group (8 rows)
    const size_t n0 = (size_t)blockIdx.x * 128;
    const size_t m0 = (size_t)blockIdx.y * 128;

    ull acc2[8][4];                  // 8 m-rows x 4 n-pairs, packed f32x2
#pragma unroll
    for (int i = 0; i < 8; ++i)
#pragma unroll
        for (int j = 0; j < 4; ++j) acc2[i][j] = 0ull;

    for (int kk = 0; kk < K; kk += 16) {
#pragma unroll
        for (int i = 0; i < 2; ++i) {
            int idx = tid + i * 256;
            int row = idx >> 2;
            int kq = (idx & 3) * 4;
            float4 v = *reinterpret_cast<const float4*>(&A[(m0 + row) * (size_t)K + kk + kq]);
            sA[row * 17 + kq + 0] = v.x;
            sA[row * 17 + kq + 1] = v.y;
            sA[row * 17 + kq + 2] = v.z;
            sA[row * 17 + kq + 3] = v.w;
        }
#pragma unroll
        for (int i = 0; i < 2; ++i) {
            int idx = tid + i * 256;
            int row = idx >> 2;
            int kq = (idx & 3) * 4;
            float4 v = *reinterpret_cast<const float4*>(&W[(n0 + row) * (size_t)K + kk + kq]);
            sB[(kq + 0) * 132 + row] = v.x;
            sB[(kq + 1) * 132 + row] = v.y;
            sB[(kq + 2) * 132 + row] = v.z;
            sB[(kq + 3) * 132 + row] = v.w;
        }
        __syncthreads();
#pragma unroll
        for (int k = 0; k < 16; ++k) {
            ull ad[8];
#pragma unroll
            for (int i = 0; i < 8; ++i) {
                float a = sA[(ty * 8 + i) * 17 + k];
                ad[i] = pack2(a, a);
            }
            ull y[4];
#pragma unroll
            for (int j = 0; j < 4; ++j)
                y[j] = ld2u(&sB[k * 132 + tx * 8 + j * 2]);
#pragma unroll
            for (int i = 0; i < 8; ++i)
#pragma unroll
                for (int j = 0; j < 4; ++j)
                    acc2[i][j] = fma2(ad[i], y[j], acc2[i][j]);
        }
        __syncthreads();
    }

    float bias[8];
#pragma unroll
    for (int j = 0; j < 8; ++j) {
        size_t n = n0 + tx * 8 + j;
        bias[j] = b1[n] + b2[n];
    }
#pragma unroll
    for (int i = 0; i < 8; ++i) {
        size_t m = m0 + ty * 8 + i;
        float* cp = &C[m * Gg + n0 + tx * 8];
        float2 v0 = unpack2(acc2[i][0]);
        float2 v1 = unpack2(acc2[i][1]);
        float2 v2 = unpack2(acc2[i][2]);
        float2 v3 = unpack2(acc2[i][3]);
        float4 o0, o1;
        o0.x = v0.x + bias[0]; o0.y = v0.y + bias[1];
        o0.z = v1.x + bias[2]; o0.w = v1.y + bias[3];
        o1.x = v2.x + bias[4]; o1.y = v2.y + bias[5];
        o1.z = v3.x + bias[6]; o1.w = v3.y + bias[7];
        *reinterpret_cast<float4*>(cp) = o0;
        *reinterpret_cast<float4*>(cp + 4) = o1;
    }
}

// ---------------- persistent LSTM recurrence -------------------------------
// Grid: 128 CTAs = 4 M-tiles (64 batch rows) x 32 col-tiles (16 h-cols).
// Each CTA: 64 gate-columns = its 16 h-cols x 4 gates (i,f,g,o), so the cell
// update is CTA-local. W_hh slice (64 rows x 512) resident in SMEM. Cell
// state c lives in registers across all 512 steps. One grid barrier / step.
// Inner product uses FFMA2 (f32x2) packed over k-pairs.
#define NCTA_R 128
#define KC 32
#define WPITCH 514   // 512 + 2 -> even pitch (8B-aligned k-pairs), conflict-free
#define HPITCH 36    // 32 + 4  -> even pitch, 16B-aligned rows

#define SMEM_REC_BYTES ((64 * WPITCH + 2 * 64 * HPITCH) * 4)

__device__ __forceinline__ float sigmoidf_(float x) {
    return 1.0f / (1.0f + __expf(-x));
}

__global__ void __launch_bounds__(256, 1)
lstm_rec(const float* __restrict__ W_hh, const float* __restrict__ xg,
         float* __restrict__ hseq)
{
    extern __shared__ float smem[];
    float* sW = smem;                          // 64 x WPITCH
    float* sH = smem + 64 * WPITCH;            // 2 x 64 x HPITCH

    const int tid = threadIdx.x;
    const int mc = tid & 15;                   // h-col within CTA
    const int mr = tid >> 4;                   // row group (4 rows each)
    const int ctaM = blockIdx.x & 3;
    const int ctaC = blockIdx.x >> 2;
    const int m0 = ctaM * 64;
    const int hc0 = ctaC * 16;
    const int hc = hc0 + mc;
    const int hrow = mr * 4;

    // Load W_hh slice: smem row (g*16+c) <- W_hh[g*H + hc0 + c][:]
    for (int idx = tid; idx < 64 * Hh; idx += 256) {
        int row = idx >> 9;
        int k = idx & 511;
        int g = row >> 4, c = row & 15;
        sW[row * WPITCH + k] = W_hh[((size_t)g * Hh + hc0 + c) * Hh + k];
    }
    __syncthreads();

    const float* wptr[4];
#pragma unroll
    for (int g = 0; g < 4; ++g) wptr[g] = sW + (g * 16 + mc) * WPITCH;

    float cstate[4] = {0.f, 0.f, 0.f, 0.f};
    unsigned phase = 0;

    for (int t = 0; t < Tt; ++t) {
        const float* hin = g_hbuf + (size_t)(t & 1) * Bb * Hh;
        float* hout = g_hbuf + (size_t)((t + 1) & 1) * Bb * Hh;

        // Issue xg loads early (consumed in epilogue)
        float xgv[4][4];
#pragma unroll
        for (int g = 0; g < 4; ++g)
#pragma unroll
            for (int r = 0; r < 4; ++r) {
                size_t brow = m0 + hrow + r;
                xgv[g][r] = __ldcg(&xg[(brow * Tt + t) * Gg + (size_t)g * Hh + hc]);
            }

        ull acc2[4][4];                        // [gate][row], f32x2 over k-pairs
#pragma unroll
        for (int g = 0; g < 4; ++g)
#pragma unroll
            for (int r = 0; r < 4; ++r) acc2[g][r] = 0ull;

        // prologue: load h chunk 0 (L2-coherent reads: L1 may be stale)
        float4 pf[2];
#pragma unroll
        for (int i = 0; i < 2; ++i) {
            int idx = tid + i * 256;
            int row = idx >> 3;
            int kq = (idx & 7) * 4;
            pf[i] = __ldcg(reinterpret_cast<const float4*>(
                &hin[(size_t)(m0 + row) * Hh + kq]));
        }
        int buf = 0;
#pragma unroll
        for (int i = 0; i < 2; ++i) {
            int idx = tid + i * 256;
            int row = idx >> 3;
            int kq = (idx & 7) * 4;
            *reinterpret_cast<float4*>(&sH[buf * (64 * HPITCH) + row * HPITCH + kq]) = pf[i];
        }
        __syncthreads();

#pragma unroll 1
        for (int cc = 0; cc < Hh / KC; ++cc) {
            if (cc < Hh / KC - 1) {
#pragma unroll
                for (int i = 0; i < 2; ++i) {
                    int idx = tid + i * 256;
                    int row = idx >> 3;
                    int kq = (idx & 7) * 4;
                    pf[i] = __ldcg(reinterpret_cast<const float4*>(
                        &hin[(size_t)(m0 + row) * Hh + (cc + 1) * KC + kq]));
                }
            }
            const float* sHb = sH + buf * (64 * HPITCH) + hrow * HPITCH;
            const int kbase = cc * KC;
#pragma unroll
            for (int kp = 0; kp < KC / 2; ++kp) {
                ull hv2[4], wv2[4];
#pragma unroll
                for (int r = 0; r < 4; ++r)
                    hv2[r] = ld2u(&sHb[r * HPITCH + 2 * kp]);
#pragma unroll
                for (int g = 0; g < 4; ++g)
                    wv2[g] = ld2u(&wptr[g][kbase + 2 * kp]);
#pragma unroll
                for (int g = 0; g < 4; ++g)
#pragma unroll
                    for (int r = 0; r < 4; ++r)
                        acc2[g][r] = fma2(wv2[g], hv2[r], acc2[g][r]);
            }
            __syncthreads();
            if (cc < Hh / KC - 1) {
                buf ^= 1;
#pragma unroll
                for (int i = 0; i < 2; ++i) {
                    int idx = tid + i * 256;
                    int row = idx >> 3;
                    int kq = (idx & 7) * 4;
                    *reinterpret_cast<float4*>(
                        &sH[buf * (64 * HPITCH) + row * HPITCH + kq]) = pf[i];
                }
                __syncthreads();
            }
        }

        // epilogue: activations + cell update (c in registers) + h write
#pragma unroll
        for (int r = 0; r < 4; ++r) {
            size_t brow = m0 + hrow + r;
            float2 vi = unpack2(acc2[0][r]);
            float2 vf = unpack2(acc2[1][r]);
            float2 vg = unpack2(acc2[2][r]);
            float2 vo = unpack2(acc2[3][r]);
            float iv = sigmoidf_(vi.x + vi.y + xgv[0][r]);
            float fv = sigmoidf_(vf.x + vf.y + xgv[1][r]);
            float gv = tanhf(vg.x + vg.y + xgv[2][r]);
            float ov = sigmoidf_(vo.x + vo.y + xgv[3][r]);
            cstate[r] = fv * cstate[r] + iv * gv;
            float hv = ov * tanhf(cstate[r]);
            hout[brow * Hh + hc] = hv;
            if (hseq) hseq[(brow * Tt + t) * Hh + hc] = hv;
        }

        // software grid barrier (release: fence-before-arrive)
        __threadfence();
        __syncthreads();
        phase += NCTA_R;
        if (tid == 0) {
            atomicAdd(&g_bar_count, 1u);
            while (*(volatile unsigned int*)&g_bar_count < phase) {
                __nanosleep(64);
            }
        }
        __syncthreads();
        __threadfence();
    }
}

// ---------------- final FC: out[b] = h_last[b,:] . W_fc + b_fc -------------
__global__ void fc_kernel(const float* __restrict__ h, const float* __restrict__ Wfc,
                          const float* __restrict__ bfc, float* __restrict__ out)
{
    int b = blockIdx.x;
    int tid = threadIdx.x;
    float s = 0.f;
    for (int k = tid; k < Hh; k += 128)
        s += h[(size_t)b * Hh + k] * Wfc[k];
#pragma unroll
    for (int o = 16; o > 0; o >>= 1) s += __shfl_xor_sync(0xffffffffu, s, o);
    __shared__ float ws[4];
    if ((tid & 31) == 0) ws[tid >> 5] = s;
    __syncthreads();
    if (tid == 0) out[b] = ws[0] + ws[1] + ws[2] + ws[3] + bfc[0];
}

// ---------------- launch ----------------------------------------------------
extern "C" void kernel_launch(void* const* d_in, const int* in_sizes, int n_in,
                              void* d_out, int out_size)
{
    (void)in_sizes; (void)n_in; (void)out_size;
    const float* x     = (const float*)d_in[0];
    const float* W_ih0 = (const float*)d_in[1];
    const float* W_hh0 = (const float*)d_in[2];
    const float* b_ih0 = (const float*)d_in[3];
    const float* b_hh0 = (const float*)d_in[4];
    const float* W_ih1 = (const float*)d_in[5];
    const float* W_hh1 = (const float*)d_in[6];
    const float* b_ih1 = (const float*)d_in[7];
    const float* b_hh1 = (const float*)d_in[8];
    const float* W_fc  = (const float*)d_in[9];
    const float* b_fc  = (const float*)d_in[10];
    float* out = (float*)d_out;

    void *p_xg = nullptr, *p_hseq = nullptr, *p_hbuf = nullptr;
    cudaGetSymbolAddress(&p_xg, g_xg);
    cudaGetSymbolAddress(&p_hseq, g_hseq);
    cudaGetSymbolAddress(&p_hbuf, g_hbuf);

    cudaFuncSetAttribute(lstm_rec, cudaFuncAttributeMaxDynamicSharedMemorySize,
                         SMEM_REC_BYTES);

    dim3 ggrid(16, 1024);  // N tiles x M tiles (2048/128, 131072/128)

    // Layer 0
    gemm_bias<<<ggrid, 256>>>(x, W_ih0, b_ih0, b_hh0, (float*)p_xg, Ii);
    init_kernel<<<1024, 256>>>();
    lstm_rec<<<NCTA_R, 256, SMEM_REC_BYTES>>>(W_hh0, (const float*)p_xg, (float*)p_hseq);

    // Layer 1
    gemm_bias<<<ggrid, 256>>>((const float*)p_hseq, W_ih1, b_ih1, b_hh1, (float*)p_xg, Hh);
    init_kernel<<<1024, 256>>>();
    lstm_rec<<<NCTA_R, 256, SMEM_REC_BYTES>>>(W_hh1, (const float*)p_xg, nullptr);

    // Final FC (h_last ends in buffer 0 since T=512 is even)
    fc_kernel<<<Bb, 128>>>((const float*)p_hbuf, W_fc, b_fc, out);
}

// round 4
// speedup vs baseline: 1.5146x; 1.5050x over previous
#include <cuda_runtime.h>
#include <cstdint>
#include <cstddef>

#define Bb 256
#define Tt 512
#define Ii 64
#define Hh 512
#define Gg 2048   // 4*H

// ---------------- tf32 mma.sync helpers (baseline PTX, sm_80+) -------------
__device__ __forceinline__ void mma_tf32(float* d, const uint32_t* a, const uint32_t* b) {
    asm volatile(
        "mma.sync.aligned.m16n8k8.row.col.f32.tf32.tf32.f32 "
        "{%0,%1,%2,%3}, {%4,%5,%6,%7}, {%8,%9}, {%0,%1,%2,%3};"
        : "+f"(d[0]), "+f"(d[1]), "+f"(d[2]), "+f"(d[3])
        : "r"(a[0]), "r"(a[1]), "r"(a[2]), "r"(a[3]), "r"(b[0]), "r"(b[1]));
}
__device__ __forceinline__ uint32_t f2tf32(float x) {
    uint32_t r; asm("cvt.rna.tf32.f32 %0, %1;" : "=r"(r) : "f"(x)); return r;
}
__device__ __forceinline__ float tf32f(float x) { return __uint_as_float(f2tf32(x)); }

// ---------------- static device scratch ------------------------------------
__device__ float g_xg[(size_t)Bb * Tt * Gg];     // 1.0 GiB gate pre-activations
__device__ float g_hseq[(size_t)Bb * Tt * Hh];   // 256 MiB layer-0 hidden seq
__device__ float g_hbuf[2 * (size_t)Bb * Hh];    // double-buffered h
__device__ unsigned int g_bar_count;             // grid barrier counter

__global__ void init_kernel() {
    unsigned idx = blockIdx.x * blockDim.x + threadIdx.x;
    if (idx < 2u * Bb * Hh) g_hbuf[idx] = 0.f;
    if (idx == 0) g_bar_count = 0u;
}

// ================= tf32 mma GEMM ============================================
// C[M,2048] = A[M,K] @ W[2048,K]^T + b1 + b2
// CTA tile 128(M) x 128(N), 8 warps (2M x 4N), warp tile 64x32.
// K staged in 32-wide chunks, double buffered, pitch-36 smem (conflict-free).
#define GP 36
#define SA_BUF (128 * GP)                 // floats per A buffer
#define GEMM_SMEM_FLOATS (4 * SA_BUF)     // A0,A1,B0,B1
#define GEMM_SMEM_BYTES (GEMM_SMEM_FLOATS * 4)

__global__ void __launch_bounds__(256)
mma_gemm(const float* __restrict__ A, const float* __restrict__ W,
         const float* __restrict__ b1, const float* __restrict__ b2,
         float* __restrict__ C, int K)
{
    extern __shared__ float sm[];
    float* sA = sm;                       // 2 buffers of [128][GP]
    float* sB = sm + 2 * SA_BUF;          // 2 buffers of [128][GP]

    const int tid = threadIdx.x;
    const int lane = tid & 31;
    const int wid = tid >> 5;
    const int gid = lane >> 2;
    const int tq = lane & 3;
    const int warpM = wid >> 2;           // 0..1
    const int warpN = wid & 3;            // 0..3
    const size_t n0 = (size_t)blockIdx.x * 128;
    const size_t m0 = (size_t)blockIdx.y * 128;
    const int NC = K >> 5;

    const int lrow = tid >> 3;            // 0..31 within 128 via 4 iters
    const int lq = tid & 7;

    float acc[4][4][4];
#pragma unroll
    for (int mt = 0; mt < 4; ++mt)
#pragma unroll
        for (int nt = 0; nt < 4; ++nt)
#pragma unroll
            for (int k = 0; k < 4; ++k) acc[mt][nt][k] = 0.f;

    float4 pa[4], pb[4];
    // prologue: ldg chunk 0
#pragma unroll
    for (int i = 0; i < 4; ++i) {
        int row = lrow + i * 32;
        pa[i] = *reinterpret_cast<const float4*>(&A[(m0 + row) * (size_t)K + lq * 4]);
        pb[i] = *reinterpret_cast<const float4*>(&W[(n0 + row) * (size_t)K + lq * 4]);
    }
#pragma unroll
    for (int i = 0; i < 4; ++i) {
        int row = lrow + i * 32;
        float* ap = &sA[row * GP + lq * 4];
        ap[0] = tf32f(pa[i].x); ap[1] = tf32f(pa[i].y); ap[2] = tf32f(pa[i].z); ap[3] = tf32f(pa[i].w);
        float* bp = &sB[row * GP + lq * 4];
        bp[0] = tf32f(pb[i].x); bp[1] = tf32f(pb[i].y); bp[2] = tf32f(pb[i].z); bp[3] = tf32f(pb[i].w);
    }
    __syncthreads();

#pragma unroll 1
    for (int c = 0; c < NC; ++c) {
        const int buf = c & 1;
        if (c + 1 < NC) {
            int k0 = (c + 1) * 32;
#pragma unroll
            for (int i = 0; i < 4; ++i) {
                int row = lrow + i * 32;
                pa[i] = *reinterpret_cast<const float4*>(&A[(m0 + row) * (size_t)K + k0 + lq * 4]);
                pb[i] = *reinterpret_cast<const float4*>(&W[(n0 + row) * (size_t)K + k0 + lq * 4]);
            }
        }
        const float* sAb = sA + buf * SA_BUF;
        const float* sBb = sB + buf * SA_BUF;
#pragma unroll
        for (int kk = 0; kk < 4; ++kk) {
            uint32_t a[4][4];
#pragma unroll
            for (int mt = 0; mt < 4; ++mt) {
                const float* ap = sAb + (warpM * 64 + mt * 16 + gid) * GP + kk * 8 + tq;
                a[mt][0] = __float_as_uint(ap[0]);
                a[mt][1] = __float_as_uint(ap[8 * GP]);
                a[mt][2] = __float_as_uint(ap[4]);
                a[mt][3] = __float_as_uint(ap[8 * GP + 4]);
            }
            uint32_t bf[4][2];
#pragma unroll
            for (int nt = 0; nt < 4; ++nt) {
                const float* bp = sBb + (warpN * 32 + nt * 8 + gid) * GP + kk * 8 + tq;
                bf[nt][0] = __float_as_uint(bp[0]);
                bf[nt][1] = __float_as_uint(bp[4]);
            }
#pragma unroll
            for (int mt = 0; mt < 4; ++mt)
#pragma unroll
                for (int nt = 0; nt < 4; ++nt)
                    mma_tf32(acc[mt][nt], a[mt], bf[nt]);
        }
        __syncthreads();
        if (c + 1 < NC) {
            float* dA = sA + (buf ^ 1) * SA_BUF;
            float* dB = sB + (buf ^ 1) * SA_BUF;
#pragma unroll
            for (int i = 0; i < 4; ++i) {
                int row = lrow + i * 32;
                float* ap = &dA[row * GP + lq * 4];
                ap[0] = tf32f(pa[i].x); ap[1] = tf32f(pa[i].y); ap[2] = tf32f(pa[i].z); ap[3] = tf32f(pa[i].w);
                float* bp = &dB[row * GP + lq * 4];
                bp[0] = tf32f(pb[i].x); bp[1] = tf32f(pb[i].y); bp[2] = tf32f(pb[i].z); bp[3] = tf32f(pb[i].w);
            }
            __syncthreads();
        }
    }

    // epilogue: bias + store
    float bias[4][2];
#pragma unroll
    for (int nt = 0; nt < 4; ++nt) {
        size_t ncol = n0 + warpN * 32 + nt * 8 + tq * 2;
        bias[nt][0] = b1[ncol] + b2[ncol];
        bias[nt][1] = b1[ncol + 1] + b2[ncol + 1];
    }
#pragma unroll
    for (int mt = 0; mt < 4; ++mt) {
        size_t r0 = m0 + warpM * 64 + mt * 16 + gid;
#pragma unroll
        for (int nt = 0; nt < 4; ++nt) {
            size_t ncol = n0 + warpN * 32 + nt * 8 + tq * 2;
            float2 v0, v1;
            v0.x = acc[mt][nt][0] + bias[nt][0];
            v0.y = acc[mt][nt][1] + bias[nt][1];
            v1.x = acc[mt][nt][2] + bias[nt][0];
            v1.y = acc[mt][nt][3] + bias[nt][1];
            *reinterpret_cast<float2*>(&C[r0 * Gg + ncol]) = v0;
            *reinterpret_cast<float2*>(&C[(r0 + 8) * Gg + ncol]) = v1;
        }
    }
}

// ================= persistent LSTM recurrence (tf32 mma) ====================
// 128 CTAs = 4 M-tiles (64 batch) x 32 col-tiles (16 hcols x 4 gates).
// Gate cols reordered j = c*4 + g so a lane pair holds all 4 gates of a slot.
// W_hh slice resident in smem (tf32). h staged in 32-wide chunks. c in regs.
#define NCTA_R 128
#define KC 32
#define RWP 516   // W pitch (conflict-free: 516 mod 32 = 4)
#define RHP 36    // h pitch
#define REC_SMEM_BYTES ((64 * RWP + 2 * 64 * RHP) * 4)

__device__ __forceinline__ float sigmoidf_(float x) {
    return 1.0f / (1.0f + __expf(-x));
}

__global__ void __launch_bounds__(256, 1)
lstm_rec(const float* __restrict__ W_hh, const float* __restrict__ xg,
         float* __restrict__ hseq)
{
    extern __shared__ float sm[];
    float* sW = sm;                  // [64][RWP]
    float* sH = sm + 64 * RWP;       // 2 x [64][RHP]

    const int tid = threadIdx.x;
    const int lane = tid & 31;
    const int wid = tid >> 5;
    const int gid = lane >> 2;
    const int tq = lane & 3;
    const int warpM = wid >> 2;      // 0..1 (32 batch rows each)
    const int warpN = wid & 3;       // 0..3 (16 gate-cols each)
    const int p = tq & 1;            // finalize mt = p
    const int chalf = tq >> 1;

    const int ctaM = blockIdx.x & 3;
    const int ctaC = blockIdx.x >> 2;
    const int m0 = ctaM * 64;
    const int hc0 = ctaC * 16;

    // Load W_hh slice, reorder rows j = c*4 + g, convert to tf32 (rna)
    for (int idx = tid; idx < 64 * Hh; idx += 256) {
        int row = idx >> 9;          // j
        int k = idx & 511;
        int c = row >> 2, g = row & 3;
        sW[row * RWP + k] = tf32f(W_hh[((size_t)g * Hh + hc0 + c) * Hh + k]);
    }
    __syncthreads();

    // finalized slots: rows m0 + warpM*32 + p*16 + row2*8 + gid, hcols per nt
    int browbase = m0 + warpM * 32 + p * 16 + gid;

    float cst[4] = {0.f, 0.f, 0.f, 0.f};
    unsigned phase = 0;

    const int lrow = tid >> 3;       // staging: 32 rows per pass (2 passes)
    const int lq = tid & 7;

    for (int t = 0; t < Tt; ++t) {
        const float* hin = g_hbuf + (size_t)(t & 1) * Bb * Hh;
        float* hout = g_hbuf + (size_t)((t + 1) & 1) * Bb * Hh;

        // xg prefetch for this thread's 4 slots x 4 gates
        float xgv[4][4];
#pragma unroll
        for (int nt = 0; nt < 2; ++nt) {
            int hcg = hc0 + warpN * 4 + nt * 2 + chalf;
#pragma unroll
            for (int row2 = 0; row2 < 2; ++row2) {
                size_t brow = browbase + row2 * 8;
#pragma unroll
                for (int g = 0; g < 4; ++g)
                    xgv[nt * 2 + row2][g] =
                        __ldcg(&xg[(brow * Tt + t) * Gg + (size_t)g * Hh + hcg]);
            }
        }

        float acc[2][2][4];
#pragma unroll
        for (int mt = 0; mt < 2; ++mt)
#pragma unroll
            for (int nt = 0; nt < 2; ++nt)
#pragma unroll
                for (int k = 0; k < 4; ++k) acc[mt][nt][k] = 0.f;

        // prologue: stage h chunk 0 (L2-coherent; L1 may be stale)
        float4 pf[2];
#pragma unroll
        for (int i = 0; i < 2; ++i) {
            int row = lrow + i * 32;
            pf[i] = __ldcg(reinterpret_cast<const float4*>(
                &hin[(size_t)(m0 + row) * Hh + lq * 4]));
        }
        int buf = 0;
#pragma unroll
        for (int i = 0; i < 2; ++i) {
            int row = lrow + i * 32;
            float* hp = &sH[buf * (64 * RHP) + row * RHP + lq * 4];
            hp[0] = tf32f(pf[i].x); hp[1] = tf32f(pf[i].y);
            hp[2] = tf32f(pf[i].z); hp[3] = tf32f(pf[i].w);
        }
        __syncthreads();

#pragma unroll 1
        for (int cc = 0; cc < Hh / KC; ++cc) {
            if (cc < Hh / KC - 1) {
#pragma unroll
                for (int i = 0; i < 2; ++i) {
                    int row = lrow + i * 32;
                    pf[i] = __ldcg(reinterpret_cast<const float4*>(
                        &hin[(size_t)(m0 + row) * Hh + (cc + 1) * KC + lq * 4]));
                }
            }
            const float* sHb = sH + buf * (64 * RHP);
            const int kb = cc * KC;
#pragma unroll
            for (int kk = 0; kk < 4; ++kk) {
                uint32_t a[2][4];
#pragma unroll
                for (int mt = 0; mt < 2; ++mt) {
                    const float* ap = sHb + (warpM * 32 + mt * 16 + gid) * RHP + kk * 8 + tq;
                    a[mt][0] = __float_as_uint(ap[0]);
                    a[mt][1] = __float_as_uint(ap[8 * RHP]);
                    a[mt][2] = __float_as_uint(ap[4]);
                    a[mt][3] = __float_as_uint(ap[8 * RHP + 4]);
                }
                uint32_t bf[2][2];
#pragma unroll
                for (int nt = 0; nt < 2; ++nt) {
                    const float* bp = sW + (warpN * 16 + nt * 8 + gid) * RWP + kb + kk * 8 + tq;
                    bf[nt][0] = __float_as_uint(bp[0]);
                    bf[nt][1] = __float_as_uint(bp[4]);
                }
#pragma unroll
                for (int mt = 0; mt < 2; ++mt)
#pragma unroll
                    for (int nt = 0; nt < 2; ++nt)
                        mma_tf32(acc[mt][nt], a[mt], bf[nt]);
            }
            __syncthreads();
            if (cc < Hh / KC - 1) {
                buf ^= 1;
#pragma unroll
                for (int i = 0; i < 2; ++i) {
                    int row = lrow + i * 32;
                    float* hp = &sH[buf * (64 * RHP) + row * RHP + lq * 4];
                    hp[0] = tf32f(pf[i].x); hp[1] = tf32f(pf[i].y);
                    hp[2] = tf32f(pf[i].z); hp[3] = tf32f(pf[i].w);
                }
                __syncthreads();
            }
        }

        // epilogue: lane-pair gate exchange + cell update + h write
#pragma unroll
        for (int nt = 0; nt < 2; ++nt) {
            int hcg = hc0 + warpN * 4 + nt * 2 + chalf;
#pragma unroll
            for (int row2 = 0; row2 < 2; ++row2) {
                float a0 = acc[0][nt][2 * row2 + 0];
                float a1 = acc[0][nt][2 * row2 + 1];
                float b0 = acc[1][nt][2 * row2 + 0];
                float b1 = acc[1][nt][2 * row2 + 1];
                float ra0 = __shfl_xor_sync(0xffffffffu, a0, 1);
                float ra1 = __shfl_xor_sync(0xffffffffu, a1, 1);
                float rb0 = __shfl_xor_sync(0xffffffffu, b0, 1);
                float rb1 = __shfl_xor_sync(0xffffffffu, b1, 1);
                float own0 = p ? b0 : a0,  own1 = p ? b1 : a1;
                float rcv0 = p ? rb0 : ra0, rcv1 = p ? rb1 : ra1;
                float gi = p ? rcv0 : own0;   // gate 0 (i)
                float gf = p ? rcv1 : own1;   // gate 1 (f)
                float gg = p ? own0 : rcv0;   // gate 2 (g)
                float go = p ? own1 : rcv1;   // gate 3 (o)
                int slot = nt * 2 + row2;
                float iv = sigmoidf_(gi + xgv[slot][0]);
                float fv = sigmoidf_(gf + xgv[slot][1]);
                float gv = tanhf(gg + xgv[slot][2]);
                float ov = sigmoidf_(go + xgv[slot][3]);
                cst[slot] = fv * cst[slot] + iv * gv;
                float hv = ov * tanhf(cst[slot]);
                size_t brow = browbase + row2 * 8;
                hout[brow * Hh + hcg] = hv;
                if (hseq) hseq[(brow * Tt + t) * Hh + hcg] = hv;
            }
        }

        // software grid barrier
        __threadfence();
        __syncthreads();
        phase += NCTA_R;
        if (tid == 0) {
            atomicAdd(&g_bar_count, 1u);
            while (*(volatile unsigned int*)&g_bar_count < phase) {
                __nanosleep(64);
            }
        }
        __syncthreads();
        __threadfence();
    }
}

// ---------------- final FC --------------------------------------------------
__global__ void fc_kernel(const float* __restrict__ h, const float* __restrict__ Wfc,
                          const float* __restrict__ bfc, float* __restrict__ out)
{
    int b = blockIdx.x;
    int tid = threadIdx.x;
    float s = 0.f;
    for (int k = tid; k < Hh; k += 128)
        s += h[(size_t)b * Hh + k] * Wfc[k];
#pragma unroll
    for (int o = 16; o > 0; o >>= 1) s += __shfl_xor_sync(0xffffffffu, s, o);
    __shared__ float ws[4];
    if ((tid & 31) == 0) ws[tid >> 5] = s;
    __syncthreads();
    if (tid == 0) out[b] = ws[0] + ws[1] + ws[2] + ws[3] + bfc[0];
}

// ---------------- launch ----------------------------------------------------
extern "C" void kernel_launch(void* const* d_in, const int* in_sizes, int n_in,
                              void* d_out, int out_size)
{
    (void)in_sizes; (void)n_in; (void)out_size;
    const float* x     = (const float*)d_in[0];
    const float* W_ih0 = (const float*)d_in[1];
    const float* W_hh0 = (const float*)d_in[2];
    const float* b_ih0 = (const float*)d_in[3];
    const float* b_hh0 = (const float*)d_in[4];
    const float* W_ih1 = (const float*)d_in[5];
    const float* W_hh1 = (const float*)d_in[6];
    const float* b_ih1 = (const float*)d_in[7];
    const float* b_hh1 = (const float*)d_in[8];
    const float* W_fc  = (const float*)d_in[9];
    const float* b_fc  = (const float*)d_in[10];
    float* out = (float*)d_out;

    void *p_xg = nullptr, *p_hseq = nullptr, *p_hbuf = nullptr;
    cudaGetSymbolAddress(&p_xg, g_xg);
    cudaGetSymbolAddress(&p_hseq, g_hseq);
    cudaGetSymbolAddress(&p_hbuf, g_hbuf);

    cudaFuncSetAttribute(mma_gemm, cudaFuncAttributeMaxDynamicSharedMemorySize,
                         GEMM_SMEM_BYTES);
    cudaFuncSetAttribute(lstm_rec, cudaFuncAttributeMaxDynamicSharedMemorySize,
                         REC_SMEM_BYTES);

    dim3 ggrid(Gg / 128, (Bb * Tt) / 128);   // (16, 1024)

    // Layer 0
    mma_gemm<<<ggrid, 256, GEMM_SMEM_BYTES>>>(x, W_ih0, b_ih0, b_hh0, (float*)p_xg, Ii);
    init_kernel<<<1024, 256>>>();
    lstm_rec<<<NCTA_R, 256, REC_SMEM_BYTES>>>(W_hh0, (const float*)p_xg, (float*)p_hseq);

    // Layer 1
    mma_gemm<<<ggrid, 256, GEMM_SMEM_BYTES>>>((const float*)p_hseq, W_ih1, b_ih1, b_hh1,
                                              (float*)p_xg, Hh);
    init_kernel<<<1024, 256>>>();
    lstm_rec<<<NCTA_R, 256, REC_SMEM_BYTES>>>(W_hh1, (const float*)p_xg, nullptr);

    // Final FC (h_last ends in buffer 0 since T=512 is even)
    fc_kernel<<<Bb, 128>>>((const float*)p_hbuf, W_fc, b_fc, out);
}

// round 5
// speedup vs baseline: 2.0611x; 1.3608x over previous
#include <cuda_runtime.h>
#include <cstdint>
#include <cstddef>

#define Bb 256
#define Tt 512
#define Ii 64
#define Hh 512
#define Gg 2048   // 4*H

// ---------------- tf32 mma.sync helpers (baseline PTX, sm_80+) -------------
__device__ __forceinline__ void mma_tf32(float* d, const uint32_t* a, const uint32_t* b) {
    asm volatile(
        "mma.sync.aligned.m16n8k8.row.col.f32.tf32.tf32.f32 "
        "{%0,%1,%2,%3}, {%4,%5,%6,%7}, {%8,%9}, {%0,%1,%2,%3};"
        : "+f"(d[0]), "+f"(d[1]), "+f"(d[2]), "+f"(d[3])
        : "r"(a[0]), "r"(a[1]), "r"(a[2]), "r"(a[3]), "r"(b[0]), "r"(b[1]));
}
__device__ __forceinline__ uint32_t f2tf32(float x) {
    uint32_t r; asm("cvt.rna.tf32.f32 %0, %1;" : "=r"(r) : "f"(x)); return r;
}
__device__ __forceinline__ float tf32f(float x) { return __uint_as_float(f2tf32(x)); }
__device__ __forceinline__ uint32_t fu(float x) { return __float_as_uint(x); }

// ---------------- static device scratch ------------------------------------
__device__ float g_xg[(size_t)Bb * Tt * Gg];     // 1.0 GiB gate pre-activations
__device__ float g_hseq[(size_t)Bb * Tt * Hh];   // 256 MiB layer-0 hidden seq
__device__ float g_hbuf[2 * (size_t)Bb * Hh];    // double-buffered h
__device__ unsigned int g_bar_count;             // grid barrier counter

__global__ void init_kernel() {
    unsigned idx = blockIdx.x * blockDim.x + threadIdx.x;
    if (idx < 2u * Bb * Hh) g_hbuf[idx] = 0.f;
    if (idx == 0) g_bar_count = 0u;
}

// ================= tf32 mma GEMM (validated in R3, unchanged) ===============
#define GP 36
#define SA_BUF (128 * GP)
#define GEMM_SMEM_BYTES (4 * SA_BUF * 4)

__global__ void __launch_bounds__(256)
mma_gemm(const float* __restrict__ A, const float* __restrict__ W,
         const float* __restrict__ b1, const float* __restrict__ b2,
         float* __restrict__ C, int K)
{
    extern __shared__ float sm[];
    float* sA = sm;
    float* sB = sm + 2 * SA_BUF;

    const int tid = threadIdx.x;
    const int lane = tid & 31;
    const int wid = tid >> 5;
    const int gid = lane >> 2;
    const int tq = lane & 3;
    const int warpM = wid >> 2;
    const int warpN = wid & 3;
    const size_t n0 = (size_t)blockIdx.x * 128;
    const size_t m0 = (size_t)blockIdx.y * 128;
    const int NC = K >> 5;

    const int lrow = tid >> 3;
    const int lq = tid & 7;

    float acc[4][4][4];
#pragma unroll
    for (int mt = 0; mt < 4; ++mt)
#pragma unroll
        for (int nt = 0; nt < 4; ++nt)
#pragma unroll
            for (int k = 0; k < 4; ++k) acc[mt][nt][k] = 0.f;

    float4 pa[4], pb[4];
#pragma unroll
    for (int i = 0; i < 4; ++i) {
        int row = lrow + i * 32;
        pa[i] = *reinterpret_cast<const float4*>(&A[(m0 + row) * (size_t)K + lq * 4]);
        pb[i] = *reinterpret_cast<const float4*>(&W[(n0 + row) * (size_t)K + lq * 4]);
    }
#pragma unroll
    for (int i = 0; i < 4; ++i) {
        int row = lrow + i * 32;
        float* ap = &sA[row * GP + lq * 4];
        ap[0] = tf32f(pa[i].x); ap[1] = tf32f(pa[i].y); ap[2] = tf32f(pa[i].z); ap[3] = tf32f(pa[i].w);
        float* bp = &sB[row * GP + lq * 4];
        bp[0] = tf32f(pb[i].x); bp[1] = tf32f(pb[i].y); bp[2] = tf32f(pb[i].z); bp[3] = tf32f(pb[i].w);
    }
    __syncthreads();

#pragma unroll 1
    for (int c = 0; c < NC; ++c) {
        const int buf = c & 1;
        if (c + 1 < NC) {
            int k0 = (c + 1) * 32;
#pragma unroll
            for (int i = 0; i < 4; ++i) {
                int row = lrow + i * 32;
                pa[i] = *reinterpret_cast<const float4*>(&A[(m0 + row) * (size_t)K + k0 + lq * 4]);
                pb[i] = *reinterpret_cast<const float4*>(&W[(n0 + row) * (size_t)K + k0 + lq * 4]);
            }
        }
        const float* sAb = sA + buf * SA_BUF;
        const float* sBb = sB + buf * SA_BUF;
#pragma unroll
        for (int kk = 0; kk < 4; ++kk) {
            uint32_t a[4][4];
#pragma unroll
            for (int mt = 0; mt < 4; ++mt) {
                const float* ap = sAb + (warpM * 64 + mt * 16 + gid) * GP + kk * 8 + tq;
                a[mt][0] = fu(ap[0]);
                a[mt][1] = fu(ap[8 * GP]);
                a[mt][2] = fu(ap[4]);
                a[mt][3] = fu(ap[8 * GP + 4]);
            }
            uint32_t bf[4][2];
#pragma unroll
            for (int nt = 0; nt < 4; ++nt) {
                const float* bp = sBb + (warpN * 32 + nt * 8 + gid) * GP + kk * 8 + tq;
                bf[nt][0] = fu(bp[0]);
                bf[nt][1] = fu(bp[4]);
            }
#pragma unroll
            for (int mt = 0; mt < 4; ++mt)
#pragma unroll
                for (int nt = 0; nt < 4; ++nt)
                    mma_tf32(acc[mt][nt], a[mt], bf[nt]);
        }
        __syncthreads();
        if (c + 1 < NC) {
            float* dA = sA + (buf ^ 1) * SA_BUF;
            float* dB = sB + (buf ^ 1) * SA_BUF;
#pragma unroll
            for (int i = 0; i < 4; ++i) {
                int row = lrow + i * 32;
                float* ap = &dA[row * GP + lq * 4];
                ap[0] = tf32f(pa[i].x); ap[1] = tf32f(pa[i].y); ap[2] = tf32f(pa[i].z); ap[3] = tf32f(pa[i].w);
                float* bp = &dB[row * GP + lq * 4];
                bp[0] = tf32f(pb[i].x); bp[1] = tf32f(pb[i].y); bp[2] = tf32f(pb[i].z); bp[3] = tf32f(pb[i].w);
            }
            __syncthreads();
        }
    }

    float bias[4][2];
#pragma unroll
    for (int nt = 0; nt < 4; ++nt) {
        size_t ncol = n0 + warpN * 32 + nt * 8 + tq * 2;
        bias[nt][0] = b1[ncol] + b2[ncol];
        bias[nt][1] = b1[ncol + 1] + b2[ncol + 1];
    }
#pragma unroll
    for (int mt = 0; mt < 4; ++mt) {
        size_t r0 = m0 + warpM * 64 + mt * 16 + gid;
#pragma unroll
        for (int nt = 0; nt < 4; ++nt) {
            size_t ncol = n0 + warpN * 32 + nt * 8 + tq * 2;
            float2 v0, v1;
            v0.x = acc[mt][nt][0] + bias[nt][0];
            v0.y = acc[mt][nt][1] + bias[nt][1];
            v1.x = acc[mt][nt][2] + bias[nt][0];
            v1.y = acc[mt][nt][3] + bias[nt][1];
            *reinterpret_cast<float2*>(&C[r0 * Gg + ncol]) = v0;
            *reinterpret_cast<float2*>(&C[(r0 + 8) * Gg + ncol]) = v1;
        }
    }
}

// ================= persistent LSTM recurrence (restructured) ================
// 128 CTAs = 4 M-tiles (64 batch) x 32 col-tiles (16 hcols = 64 gatecols,
// packed j = cl*4 + g). 256 threads = 8 warps = 2(M) x 2(N) x 2(K-split).
// Warp tile 32m x 32gc x 64k-per-chunk. KC=128 -> 4 chunks/step.
// W_hh resident in smem (tf32). xg staged via smem (coalesced LDG).
// K-split partials reduced in smem (aliased onto free h buffer).
#define NCTA_R 128
#define RWP 516                       // W pitch
#define RHP 132                       // h pitch (KC=128 + 4)
#define SH_BUF (64 * RHP)             // floats per h buffer
#define XGP 68                        // xg pitch
#define REC_SMEM_FLOATS (64 * RWP + 2 * SH_BUF + 64 * XGP)
#define REC_SMEM_BYTES (REC_SMEM_FLOATS * 4)   // 217,088 B

__device__ __forceinline__ float sigmoidf_(float x) {
    return 1.0f / (1.0f + __expf(-x));
}

__global__ void __launch_bounds__(256, 1)
lstm_rec(const float* __restrict__ W_hh, const float* __restrict__ xg,
         float* __restrict__ hseq)
{
    extern __shared__ float sm[];
    float* sW  = sm;                      // [64][516]
    float* sH  = sm + 64 * RWP;           // 2 x [64][132]
    float* sXG = sH + 2 * SH_BUF;         // [64][68]
    float* sRed = sH;                     // alias h buffer 0 (free at reduction)

    const int tid = threadIdx.x;
    const int lane = tid & 31;
    const int wid = tid >> 5;
    const int wK = wid >> 2;              // 0..1 k-split
    const int wM = (wid >> 1) & 1;        // 0..1 (32 rows)
    const int wN = wid & 1;               // 0..1 (32 gatecols)
    const int gid = lane >> 2;
    const int tq = lane & 3;
    const int p = lane & 1;

    const int ctaM = blockIdx.x & 3;
    const int ctaC = blockIdx.x >> 2;
    const int m0 = ctaM * 64;
    const int hc0 = ctaC * 16;

    // W_hh slice -> smem (tf32), row j = cl*4 + g  <-  W_hh[g*H + hc0+cl][k]
    for (int idx = tid; idx < 64 * 512; idx += 256) {
        int j = idx >> 9, k = idx & 511;
        sW[j * RWP + k] = tf32f(W_hh[((size_t)(j & 3) * Hh + hc0 + (j >> 2)) * Hh + k]);
    }
    __syncthreads();

    float cst[8];
#pragma unroll
    for (int s = 0; s < 8; ++s) cst[s] = 0.f;
    unsigned phase = 0;

    for (int t = 0; t < Tt; ++t) {
        const float* hin = g_hbuf + (size_t)(t & 1) * Bb * Hh;
        float* hout = g_hbuf + (size_t)((t + 1) & 1) * Bb * Hh;

        // ---- xg tile LDG (coalesced; consumed in epilogue) ----
        float4 xpf[4];
#pragma unroll
        for (int it = 0; it < 4; ++it) {
            int i = tid + it * 256;
            int row = i >> 4, qc = i & 15;
            const float* src = &xg[((size_t)(m0 + row) * Tt + t) * Gg
                                   + (size_t)(qc >> 2) * Hh + hc0 + (qc & 3) * 4];
            xpf[it] = __ldcg(reinterpret_cast<const float4*>(src));
        }

        // ---- h chunk 0 stage ----
        float4 pf[8];
#pragma unroll
        for (int it = 0; it < 8; ++it) {
            int i = tid + it * 256;
            int r = i >> 5, q = i & 31;
            pf[it] = __ldcg(reinterpret_cast<const float4*>(
                &hin[(size_t)(m0 + r) * Hh + q * 4]));
        }
        int buf = 0;
#pragma unroll
        for (int it = 0; it < 8; ++it) {
            int i = tid + it * 256;
            int r = i >> 5, q = i & 31;
            float* d = &sH[buf * SH_BUF + r * RHP + q * 4];
            d[0] = tf32f(pf[it].x); d[1] = tf32f(pf[it].y);
            d[2] = tf32f(pf[it].z); d[3] = tf32f(pf[it].w);
        }
        __syncthreads();

        float acc[2][4][4];
#pragma unroll
        for (int mt = 0; mt < 2; ++mt)
#pragma unroll
            for (int nt = 0; nt < 4; ++nt)
#pragma unroll
                for (int k = 0; k < 4; ++k) acc[mt][nt][k] = 0.f;

#pragma unroll 1
        for (int cc = 0; cc < 4; ++cc) {
            if (cc < 3) {
                int kb = (cc + 1) * 128;
#pragma unroll
                for (int it = 0; it < 8; ++it) {
                    int i = tid + it * 256;
                    int r = i >> 5, q = i & 31;
                    pf[it] = __ldcg(reinterpret_cast<const float4*>(
                        &hin[(size_t)(m0 + r) * Hh + kb + q * 4]));
                }
            }
            const float* sHb = sH + buf * SH_BUF;
            const int kq0 = wK * 64;
            const int wcol0 = cc * 128 + kq0;
#pragma unroll
            for (int kk = 0; kk < 8; ++kk) {
                uint32_t a[2][4];
#pragma unroll
                for (int mt = 0; mt < 2; ++mt) {
                    const float* ap = sHb + (wM * 32 + mt * 16 + gid) * RHP + kq0 + kk * 8 + tq;
                    a[mt][0] = fu(ap[0]);
                    a[mt][1] = fu(ap[8 * RHP]);
                    a[mt][2] = fu(ap[4]);
                    a[mt][3] = fu(ap[8 * RHP + 4]);
                }
#pragma unroll
                for (int nt = 0; nt < 4; ++nt) {
                    const float* bp = sW + (wN * 32 + nt * 8 + gid) * RWP + wcol0 + kk * 8 + tq;
                    uint32_t bfr[2];
                    bfr[0] = fu(bp[0]);
                    bfr[1] = fu(bp[4]);
#pragma unroll
                    for (int mt = 0; mt < 2; ++mt)
                        mma_tf32(acc[mt][nt], a[mt], bfr);
                }
            }
            if (cc == 0) {
                // stage xg tile (LDGs issued at step start)
#pragma unroll
                for (int it = 0; it < 4; ++it) {
                    int i = tid + it * 256;
                    int row = i >> 4, qc = i & 15;
                    *reinterpret_cast<float4*>(&sXG[row * XGP + qc * 4]) = xpf[it];
                }
            }
            __syncthreads();
            if (cc < 3) {
                buf ^= 1;
#pragma unroll
                for (int it = 0; it < 8; ++it) {
                    int i = tid + it * 256;
                    int r = i >> 5, q = i & 31;
                    float* d = &sH[buf * SH_BUF + r * RHP + q * 4];
                    d[0] = tf32f(pf[it].x); d[1] = tf32f(pf[it].y);
                    d[2] = tf32f(pf[it].z); d[3] = tf32f(pf[it].w);
                }
                __syncthreads();
            }
        }

        // ---- K-split reduction (sRed aliases h buffer 0, now free) ----
        if (wK == 1) {
            int pair = wM * 2 + wN;
#pragma unroll
            for (int mt = 0; mt < 2; ++mt)
#pragma unroll
                for (int nt = 0; nt < 4; ++nt)
#pragma unroll
                    for (int r = 0; r < 4; ++r)
                        sRed[pair * 1024 + ((mt * 4 + nt) * 4 + r) * 32 + lane] = acc[mt][nt][r];
        }
        __syncthreads();

        if (wK == 0) {
            int pair = wM * 2 + wN;
#pragma unroll
            for (int mt = 0; mt < 2; ++mt)
#pragma unroll
                for (int nt = 0; nt < 4; ++nt)
#pragma unroll
                    for (int r = 0; r < 4; ++r)
                        acc[mt][nt][r] += sRed[pair * 1024 + ((mt * 4 + nt) * 4 + r) * 32 + lane];

            // ---- epilogue: gate exchange + cell update + h write ----
#pragma unroll
            for (int mt = 0; mt < 2; ++mt) {
                int rl = wM * 32 + mt * 16 + gid + p * 8;
                size_t grow = m0 + rl;
#pragma unroll
                for (int nt = 0; nt < 4; ++nt) {
                    float s0 = p ? acc[mt][nt][0] : acc[mt][nt][2];
                    float s1 = p ? acc[mt][nt][1] : acc[mt][nt][3];
                    float r0 = __shfl_xor_sync(0xffffffffu, s0, 1);
                    float r1 = __shfl_xor_sync(0xffffffffu, s1, 1);
                    float gi = p ? r0 : acc[mt][nt][0];
                    float gf = p ? r1 : acc[mt][nt][1];
                    float gg = p ? acc[mt][nt][2] : r0;
                    float go = p ? acc[mt][nt][3] : r1;
                    int cl = wN * 8 + nt * 2 + (tq >> 1);
                    const float* xp = &sXG[rl * XGP + cl];
                    float iv = sigmoidf_(gi + xp[0]);
                    float fv = sigmoidf_(gf + xp[16]);
                    float gv = tanhf(gg + xp[32]);
                    float ov = sigmoidf_(go + xp[48]);
                    int slot = mt * 4 + nt;
                    cst[slot] = fv * cst[slot] + iv * gv;
                    float hv = ov * tanhf(cst[slot]);
                    hout[grow * Hh + hc0 + cl] = hv;
                    if (hseq) hseq[(grow * Tt + t) * Hh + hc0 + cl] = hv;
                }
            }
        }

        // ---- software grid barrier (release/acquire) ----
        __threadfence();
        __syncthreads();
        phase += NCTA_R;
        if (tid == 0) {
            atomicAdd(&g_bar_count, 1u);
            while (*(volatile unsigned int*)&g_bar_count < phase) {
                __nanosleep(64);
            }
        }
        __syncthreads();
        __threadfence();
    }
}

// ---------------- final FC --------------------------------------------------
__global__ void fc_kernel(const float* __restrict__ h, const float* __restrict__ Wfc,
                          const float* __restrict__ bfc, float* __restrict__ out)
{
    int b = blockIdx.x;
    int tid = threadIdx.x;
    float s = 0.f;
    for (int k = tid; k < Hh; k += 128)
        s += h[(size_t)b * Hh + k] * Wfc[k];
#pragma unroll
    for (int o = 16; o > 0; o >>= 1) s += __shfl_xor_sync(0xffffffffu, s, o);
    __shared__ float ws[4];
    if ((tid & 31) == 0) ws[tid >> 5] = s;
    __syncthreads();
    if (tid == 0) out[b] = ws[0] + ws[1] + ws[2] + ws[3] + bfc[0];
}

// ---------------- launch ----------------------------------------------------
extern "C" void kernel_launch(void* const* d_in, const int* in_sizes, int n_in,
                              void* d_out, int out_size)
{
    (void)in_sizes; (void)n_in; (void)out_size;
    const float* x     = (const float*)d_in[0];
    const float* W_ih0 = (const float*)d_in[1];
    const float* W_hh0 = (const float*)d_in[2];
    const float* b_ih0 = (const float*)d_in[3];
    const float* b_hh0 = (const float*)d_in[4];
    const float* W_ih1 = (const float*)d_in[5];
    const float* W_hh1 = (const float*)d_in[6];
    const float* b_ih1 = (const float*)d_in[7];
    const float* b_hh1 = (const float*)d_in[8];
    const float* W_fc  = (const float*)d_in[9];
    const float* b_fc  = (const float*)d_in[10];
    float* out = (float*)d_out;

    void *p_xg = nullptr, *p_hseq = nullptr, *p_hbuf = nullptr;
    cudaGetSymbolAddress(&p_xg, g_xg);
    cudaGetSymbolAddress(&p_hseq, g_hseq);
    cudaGetSymbolAddress(&p_hbuf, g_hbuf);

    cudaFuncSetAttribute(mma_gemm, cudaFuncAttributeMaxDynamicSharedMemorySize,
                         GEMM_SMEM_BYTES);
    cudaFuncSetAttribute(lstm_rec, cudaFuncAttributeMaxDynamicSharedMemorySize,
                         REC_SMEM_BYTES);

    dim3 ggrid(Gg / 128, (Bb * Tt) / 128);   // (16, 1024)

    // Layer 0
    mma_gemm<<<ggrid, 256, GEMM_SMEM_BYTES>>>(x, W_ih0, b_ih0, b_hh0, (float*)p_xg, Ii);
    init_kernel<<<1024, 256>>>();
    lstm_rec<<<NCTA_R, 256, REC_SMEM_BYTES>>>(W_hh0, (const float*)p_xg, (float*)p_hseq);

    // Layer 1
    mma_gemm<<<ggrid, 256, GEMM_SMEM_BYTES>>>((const float*)p_hseq, W_ih1, b_ih1, b_hh1,
                                              (float*)p_xg, Hh);
    init_kernel<<<1024, 256>>>();
    lstm_rec<<<NCTA_R, 256, REC_SMEM_BYTES>>>(W_hh1, (const float*)p_xg, nullptr);

    // Final FC (h_last ends in buffer 0 since T=512 is even)
    fc_kernel<<<Bb, 128>>>((const float*)p_hbuf, W_fc, b_fc, out);
}

// round 6
// speedup vs baseline: 2.2196x; 1.0769x over previous
#include <cuda_runtime.h>
#include <cstdint>
#include <cstddef>

#define Bb 256
#define Tt 512
#define Ii 64
#define Hh 512
#define Gg 2048   // 4*H

// ---------------- tf32 mma.sync helpers (baseline PTX, sm_80+) -------------
__device__ __forceinline__ void mma_tf32(float* d, const uint32_t* a, const uint32_t* b) {
    asm volatile(
        "mma.sync.aligned.m16n8k8.row.col.f32.tf32.tf32.f32 "
        "{%0,%1,%2,%3}, {%4,%5,%6,%7}, {%8,%9}, {%0,%1,%2,%3};"
        : "+f"(d[0]), "+f"(d[1]), "+f"(d[2]), "+f"(d[3])
        : "r"(a[0]), "r"(a[1]), "r"(a[2]), "r"(a[3]), "r"(b[0]), "r"(b[1]));
}
__device__ __forceinline__ uint32_t f2tf32(float x) {
    uint32_t r; asm("cvt.rna.tf32.f32 %0, %1;" : "=r"(r) : "f"(x)); return r;
}
__device__ __forceinline__ float tf32f(float x) { return __uint_as_float(f2tf32(x)); }
__device__ __forceinline__ uint32_t fu(float x) { return __float_as_uint(x); }

// ---------------- static device scratch ------------------------------------
__device__ float g_xg[(size_t)Bb * Tt * Gg];     // 1.0 GiB gate pre-activations
__device__ float g_hseq[(size_t)Bb * Tt * Hh];   // 256 MiB layer-0 hidden seq
__device__ float g_hbuf[2 * (size_t)Bb * Hh];    // double-buffered h
__device__ unsigned int g_bar_count;             // grid barrier counter

__global__ void init_kernel() {
    unsigned idx = blockIdx.x * blockDim.x + threadIdx.x;
    if (idx < 2u * Bb * Hh) g_hbuf[idx] = 0.f;
    if (idx == 0) g_bar_count = 0u;
}

// ================= tf32 mma GEMM (validated, unchanged) =====================
#define GP 36
#define SA_BUF (128 * GP)
#define GEMM_SMEM_BYTES (4 * SA_BUF * 4)

__global__ void __launch_bounds__(256)
mma_gemm(const float* __restrict__ A, const float* __restrict__ W,
         const float* __restrict__ b1, const float* __restrict__ b2,
         float* __restrict__ C, int K)
{
    extern __shared__ float sm[];
    float* sA = sm;
    float* sB = sm + 2 * SA_BUF;

    const int tid = threadIdx.x;
    const int lane = tid & 31;
    const int wid = tid >> 5;
    const int gid = lane >> 2;
    const int tq = lane & 3;
    const int warpM = wid >> 2;
    const int warpN = wid & 3;
    const size_t n0 = (size_t)blockIdx.x * 128;
    const size_t m0 = (size_t)blockIdx.y * 128;
    const int NC = K >> 5;

    const int lrow = tid >> 3;
    const int lq = tid & 7;

    float acc[4][4][4];
#pragma unroll
    for (int mt = 0; mt < 4; ++mt)
#pragma unroll
        for (int nt = 0; nt < 4; ++nt)
#pragma unroll
            for (int k = 0; k < 4; ++k) acc[mt][nt][k] = 0.f;

    float4 pa[4], pb[4];
#pragma unroll
    for (int i = 0; i < 4; ++i) {
        int row = lrow + i * 32;
        pa[i] = *reinterpret_cast<const float4*>(&A[(m0 + row) * (size_t)K + lq * 4]);
        pb[i] = *reinterpret_cast<const float4*>(&W[(n0 + row) * (size_t)K + lq * 4]);
    }
#pragma unroll
    for (int i = 0; i < 4; ++i) {
        int row = lrow + i * 32;
        float* ap = &sA[row * GP + lq * 4];
        ap[0] = tf32f(pa[i].x); ap[1] = tf32f(pa[i].y); ap[2] = tf32f(pa[i].z); ap[3] = tf32f(pa[i].w);
        float* bp = &sB[row * GP + lq * 4];
        bp[0] = tf32f(pb[i].x); bp[1] = tf32f(pb[i].y); bp[2] = tf32f(pb[i].z); bp[3] = tf32f(pb[i].w);
    }
    __syncthreads();

#pragma unroll 1
    for (int c = 0; c < NC; ++c) {
        const int buf = c & 1;
        if (c + 1 < NC) {
            int k0 = (c + 1) * 32;
#pragma unroll
            for (int i = 0; i < 4; ++i) {
                int row = lrow + i * 32;
                pa[i] = *reinterpret_cast<const float4*>(&A[(m0 + row) * (size_t)K + k0 + lq * 4]);
                pb[i] = *reinterpret_cast<const float4*>(&W[(n0 + row) * (size_t)K + k0 + lq * 4]);
            }
        }
        const float* sAb = sA + buf * SA_BUF;
        const float* sBb = sB + buf * SA_BUF;
#pragma unroll
        for (int kk = 0; kk < 4; ++kk) {
            uint32_t a[4][4];
#pragma unroll
            for (int mt = 0; mt < 4; ++mt) {
                const float* ap = sAb + (warpM * 64 + mt * 16 + gid) * GP + kk * 8 + tq;
                a[mt][0] = fu(ap[0]);
                a[mt][1] = fu(ap[8 * GP]);
                a[mt][2] = fu(ap[4]);
                a[mt][3] = fu(ap[8 * GP + 4]);
            }
            uint32_t bf[4][2];
#pragma unroll
            for (int nt = 0; nt < 4; ++nt) {
                const float* bp = sBb + (warpN * 32 + nt * 8 + gid) * GP + kk * 8 + tq;
                bf[nt][0] = fu(bp[0]);
                bf[nt][1] = fu(bp[4]);
            }
#pragma unroll
            for (int mt = 0; mt < 4; ++mt)
#pragma unroll
                for (int nt = 0; nt < 4; ++nt)
                    mma_tf32(acc[mt][nt], a[mt], bf[nt]);
        }
        __syncthreads();
        if (c + 1 < NC) {
            float* dA = sA + (buf ^ 1) * SA_BUF;
            float* dB = sB + (buf ^ 1) * SA_BUF;
#pragma unroll
            for (int i = 0; i < 4; ++i) {
                int row = lrow + i * 32;
                float* ap = &dA[row * GP + lq * 4];
                ap[0] = tf32f(pa[i].x); ap[1] = tf32f(pa[i].y); ap[2] = tf32f(pa[i].z); ap[3] = tf32f(pa[i].w);
                float* bp = &dB[row * GP + lq * 4];
                bp[0] = tf32f(pb[i].x); bp[1] = tf32f(pb[i].y); bp[2] = tf32f(pb[i].z); bp[3] = tf32f(pb[i].w);
            }
            __syncthreads();
        }
    }

    float bias[4][2];
#pragma unroll
    for (int nt = 0; nt < 4; ++nt) {
        size_t ncol = n0 + warpN * 32 + nt * 8 + tq * 2;
        bias[nt][0] = b1[ncol] + b2[ncol];
        bias[nt][1] = b1[ncol + 1] + b2[ncol + 1];
    }
#pragma unroll
    for (int mt = 0; mt < 4; ++mt) {
        size_t r0 = m0 + warpM * 64 + mt * 16 + gid;
#pragma unroll
        for (int nt = 0; nt < 4; ++nt) {
            size_t ncol = n0 + warpN * 32 + nt * 8 + tq * 2;
            float2 v0, v1;
            v0.x = acc[mt][nt][0] + bias[nt][0];
            v0.y = acc[mt][nt][1] + bias[nt][1];
            v1.x = acc[mt][nt][2] + bias[nt][0];
            v1.y = acc[mt][nt][3] + bias[nt][1];
            *reinterpret_cast<float2*>(&C[r0 * Gg + ncol]) = v0;
            *reinterpret_cast<float2*>(&C[(r0 + 8) * Gg + ncol]) = v1;
        }
    }
}

// ================= persistent LSTM recurrence ================================
// 128 CTAs = 4 M-tiles x 32 col-tiles. 8 warps = 2M x 2N x 2K-split.
// Single-sync-per-chunk pipeline, acq/rel grid barrier (no L1 flush),
// cross-step xg prefetch hidden behind the barrier.
#define NCTA_R 128
#define RWP 516
#define RHP 132
#define SH_BUF (64 * RHP)
#define XGP 68
#define REC_SMEM_FLOATS (64 * RWP + 2 * SH_BUF + 64 * XGP)
#define REC_SMEM_BYTES (REC_SMEM_FLOATS * 4)

__device__ __forceinline__ float sigmoidf_(float x) {
    return 1.0f / (1.0f + __expf(-x));
}

__global__ void __launch_bounds__(256, 1)
lstm_rec(const float* __restrict__ W_hh, const float* __restrict__ xg,
         float* __restrict__ hseq)
{
    extern __shared__ float sm[];
    float* sW  = sm;                      // [64][516]
    float* sH  = sm + 64 * RWP;           // 2 x [64][132]
    float* sXG = sH + 2 * SH_BUF;         // [64][68]
    float* sRed = sH;                     // alias h buffer 0

    const int tid = threadIdx.x;
    const int lane = tid & 31;
    const int wid = tid >> 5;
    const int wK = wid >> 2;
    const int wM = (wid >> 1) & 1;
    const int wN = wid & 1;
    const int gid = lane >> 2;
    const int tq = lane & 3;
    const int p = lane & 1;

    const int ctaM = blockIdx.x & 3;
    const int ctaC = blockIdx.x >> 2;
    const int m0 = ctaM * 64;
    const int hc0 = ctaC * 16;

    // W_hh slice -> smem (tf32), row j = cl*4 + g
    for (int idx = tid; idx < 64 * 512; idx += 256) {
        int j = idx >> 9, k = idx & 511;
        sW[j * RWP + k] = tf32f(W_hh[((size_t)(j & 3) * Hh + hc0 + (j >> 2)) * Hh + k]);
    }
    __syncthreads();

    float cst[8];
#pragma unroll
    for (int s = 0; s < 8; ++s) cst[s] = 0.f;
    unsigned phase = 0;

    // ---- xg prefetch for t = 0 ----
    float4 xpf[4];
#pragma unroll
    for (int it = 0; it < 4; ++it) {
        int i = tid + it * 256;
        int row = i >> 4, qc = i & 15;
        xpf[it] = __ldcg(reinterpret_cast<const float4*>(
            &xg[((size_t)(m0 + row) * Tt + 0) * Gg + (size_t)(qc >> 2) * Hh + hc0 + (qc & 3) * 4]));
    }

    for (int t = 0; t < Tt; ++t) {
        const float* hin = g_hbuf + (size_t)(t & 1) * Bb * Hh;
        float* hout = g_hbuf + (size_t)((t + 1) & 1) * Bb * Hh;

        // ---- h chunk 0 LDG ----
        float4 pf[8];
#pragma unroll
        for (int it = 0; it < 8; ++it) {
            int i = tid + it * 256;
            int r = i >> 5, q = i & 31;
            pf[it] = __ldcg(reinterpret_cast<const float4*>(
                &hin[(size_t)(m0 + r) * Hh + q * 4]));
        }
        // ---- stage xg tile (regs prefetched last step) ----
#pragma unroll
        for (int it = 0; it < 4; ++it) {
            int i = tid + it * 256;
            int row = i >> 4, qc = i & 15;
            *reinterpret_cast<float4*>(&sXG[row * XGP + qc * 4]) = xpf[it];
        }
        // ---- stage h chunk 0 -> buf 0 ----
#pragma unroll
        for (int it = 0; it < 8; ++it) {
            int i = tid + it * 256;
            int r = i >> 5, q = i & 31;
            float* d = &sH[r * RHP + q * 4];
            d[0] = tf32f(pf[it].x); d[1] = tf32f(pf[it].y);
            d[2] = tf32f(pf[it].z); d[3] = tf32f(pf[it].w);
        }
        __syncthreads();

        float acc[2][4][4];
#pragma unroll
        for (int mt = 0; mt < 2; ++mt)
#pragma unroll
            for (int nt = 0; nt < 4; ++nt)
#pragma unroll
                for (int k = 0; k < 4; ++k) acc[mt][nt][k] = 0.f;

        // ---- 4-chunk mainloop, ONE sync per chunk ----
#pragma unroll
        for (int cc = 0; cc < 4; ++cc) {
            if (cc < 3) {
                int kb = (cc + 1) * 128;
#pragma unroll
                for (int it = 0; it < 8; ++it) {
                    int i = tid + it * 256;
                    int r = i >> 5, q = i & 31;
                    pf[it] = __ldcg(reinterpret_cast<const float4*>(
                        &hin[(size_t)(m0 + r) * Hh + kb + q * 4]));
                }
            }
            const float* sHb = sH + (cc & 1) * SH_BUF;
            const int kq0 = wK * 64;
            const int wcol0 = cc * 128 + kq0;
#pragma unroll
            for (int kk = 0; kk < 8; ++kk) {
                uint32_t a[2][4];
#pragma unroll
                for (int mt = 0; mt < 2; ++mt) {
                    const float* ap = sHb + (wM * 32 + mt * 16 + gid) * RHP + kq0 + kk * 8 + tq;
                    a[mt][0] = fu(ap[0]);
                    a[mt][1] = fu(ap[8 * RHP]);
                    a[mt][2] = fu(ap[4]);
                    a[mt][3] = fu(ap[8 * RHP + 4]);
                }
#pragma unroll
                for (int nt = 0; nt < 4; ++nt) {
                    const float* bp = sW + (wN * 32 + nt * 8 + gid) * RWP + wcol0 + kk * 8 + tq;
                    uint32_t bfr[2];
                    bfr[0] = fu(bp[0]);
                    bfr[1] = fu(bp[4]);
#pragma unroll
                    for (int mt = 0; mt < 2; ++mt)
                        mma_tf32(acc[mt][nt], a[mt], bfr);
                }
            }
            if (cc < 3) {
                // restage chunk cc+1 into the buffer NOT used by this chunk's mma
                float* dst = sH + ((cc + 1) & 1) * SH_BUF;
#pragma unroll
                for (int it = 0; it < 8; ++it) {
                    int i = tid + it * 256;
                    int r = i >> 5, q = i & 31;
                    float* d = &dst[r * RHP + q * 4];
                    d[0] = tf32f(pf[it].x); d[1] = tf32f(pf[it].y);
                    d[2] = tf32f(pf[it].z); d[3] = tf32f(pf[it].w);
                }
            } else if (wK == 1) {
                // K-split partials -> sRed (aliases buf0: chunk2 done being read)
                int pair = wM * 2 + wN;
#pragma unroll
                for (int mt = 0; mt < 2; ++mt)
#pragma unroll
                    for (int nt = 0; nt < 4; ++nt)
#pragma unroll
                        for (int r = 0; r < 4; ++r)
                            sRed[pair * 1024 + ((mt * 4 + nt) * 4 + r) * 32 + lane] = acc[mt][nt][r];
            }
            __syncthreads();
        }

        if (wK == 0) {
            int pair = wM * 2 + wN;
#pragma unroll
            for (int mt = 0; mt < 2; ++mt)
#pragma unroll
                for (int nt = 0; nt < 4; ++nt)
#pragma unroll
                    for (int r = 0; r < 4; ++r)
                        acc[mt][nt][r] += sRed[pair * 1024 + ((mt * 4 + nt) * 4 + r) * 32 + lane];

            // ---- epilogue: gate exchange + cell update + h write ----
#pragma unroll
            for (int mt = 0; mt < 2; ++mt) {
                int rl = wM * 32 + mt * 16 + gid + p * 8;
                size_t grow = m0 + rl;
#pragma unroll
                for (int nt = 0; nt < 4; ++nt) {
                    float s0 = p ? acc[mt][nt][0] : acc[mt][nt][2];
                    float s1 = p ? acc[mt][nt][1] : acc[mt][nt][3];
                    float r0 = __shfl_xor_sync(0xffffffffu, s0, 1);
                    float r1 = __shfl_xor_sync(0xffffffffu, s1, 1);
                    float gi = p ? r0 : acc[mt][nt][0];
                    float gf = p ? r1 : acc[mt][nt][1];
                    float gg = p ? acc[mt][nt][2] : r0;
                    float go = p ? acc[mt][nt][3] : r1;
                    int cl = wN * 8 + nt * 2 + (tq >> 1);
                    const float* xp = &sXG[rl * XGP + cl];
                    float iv = sigmoidf_(gi + xp[0]);
                    float fv = sigmoidf_(gf + xp[16]);
                    float gv = tanhf(gg + xp[32]);
                    float ov = sigmoidf_(go + xp[48]);
                    int slot = mt * 4 + nt;
                    cst[slot] = fv * cst[slot] + iv * gv;
                    float hv = ov * tanhf(cst[slot]);
                    hout[grow * Hh + hc0 + cl] = hv;
                    if (hseq) hseq[(grow * Tt + t) * Hh + hc0 + cl] = hv;
                }
            }
        }

        // ---- xg prefetch for t+1 (hidden behind barrier) ----
        if (t + 1 < Tt) {
#pragma unroll
            for (int it = 0; it < 4; ++it) {
                int i = tid + it * 256;
                int row = i >> 4, qc = i & 15;
                xpf[it] = __ldcg(reinterpret_cast<const float4*>(
                    &xg[((size_t)(m0 + row) * Tt + (t + 1)) * Gg
                        + (size_t)(qc >> 2) * Hh + hc0 + (qc & 3) * 4]));
            }
        }

        // ---- grid barrier: release arrive + acquire spin (no L1 flush) ----
        __syncthreads();
        phase += NCTA_R;
        if (tid == 0) {
            asm volatile("red.release.gpu.add.u32 [%0], %1;"
                         :: "l"(&g_bar_count), "r"(1u) : "memory");
            unsigned v;
            while (true) {
                asm volatile("ld.acquire.gpu.u32 %0, [%1];"
                             : "=r"(v) : "l"(&g_bar_count) : "memory");
                if (v >= phase) break;
                __nanosleep(32);
            }
        }
        __syncthreads();
    }
}

// ---------------- final FC --------------------------------------------------
__global__ void fc_kernel(const float* __restrict__ h, const float* __restrict__ Wfc,
                          const float* __restrict__ bfc, float* __restrict__ out)
{
    int b = blockIdx.x;
    int tid = threadIdx.x;
    float s = 0.f;
    for (int k = tid; k < Hh; k += 128)
        s += h[(size_t)b * Hh + k] * Wfc[k];
#pragma unroll
    for (int o = 16; o > 0; o >>= 1) s += __shfl_xor_sync(0xffffffffu, s, o);
    __shared__ float ws[4];
    if ((tid & 31) == 0) ws[tid >> 5] = s;
    __syncthreads();
    if (tid == 0) out[b] = ws[0] + ws[1] + ws[2] + ws[3] + bfc[0];
}

// ---------------- launch ----------------------------------------------------
extern "C" void kernel_launch(void* const* d_in, const int* in_sizes, int n_in,
                              void* d_out, int out_size)
{
    (void)in_sizes; (void)n_in; (void)out_size;
    const float* x     = (const float*)d_in[0];
    const float* W_ih0 = (const float*)d_in[1];
    const float* W_hh0 = (const float*)d_in[2];
    const float* b_ih0 = (const float*)d_in[3];
    const float* b_hh0 = (const float*)d_in[4];
    const float* W_ih1 = (const float*)d_in[5];
    const float* W_hh1 = (const float*)d_in[6];
    const float* b_ih1 = (const float*)d_in[7];
    const float* b_hh1 = (const float*)d_in[8];
    const float* W_fc  = (const float*)d_in[9];
    const float* b_fc  = (const float*)d_in[10];
    float* out = (float*)d_out;

    void *p_xg = nullptr, *p_hseq = nullptr, *p_hbuf = nullptr;
    cudaGetSymbolAddress(&p_xg, g_xg);
    cudaGetSymbolAddress(&p_hseq, g_hseq);
    cudaGetSymbolAddress(&p_hbuf, g_hbuf);

    cudaFuncSetAttribute(mma_gemm, cudaFuncAttributeMaxDynamicSharedMemorySize,
                         GEMM_SMEM_BYTES);
    cudaFuncSetAttribute(lstm_rec, cudaFuncAttributeMaxDynamicSharedMemorySize,
                         REC_SMEM_BYTES);

    dim3 ggrid(Gg / 128, (Bb * Tt) / 128);   // (16, 1024)

    // Layer 0
    mma_gemm<<<ggrid, 256, GEMM_SMEM_BYTES>>>(x, W_ih0, b_ih0, b_hh0, (float*)p_xg, Ii);
    init_kernel<<<1024, 256>>>();
    lstm_rec<<<NCTA_R, 256, REC_SMEM_BYTES>>>(W_hh0, (const float*)p_xg, (float*)p_hseq);

    // Layer 1
    mma_gemm<<<ggrid, 256, GEMM_SMEM_BYTES>>>((const float*)p_hseq, W_ih1, b_ih1, b_hh1,
                                              (float*)p_xg, Hh);
    init_kernel<<<1024, 256>>>();
    lstm_rec<<<NCTA_R, 256, REC_SMEM_BYTES>>>(W_hh1, (const float*)p_xg, nullptr);

    // Final FC (h_last ends in buffer 0 since T=512 is even)
    fc_kernel<<<Bb, 128>>>((const float*)p_hbuf, W_fc, b_fc, out);
}

// round 7
// speedup vs baseline: 2.3468x; 1.0573x over previous
#include <cuda_runtime.h>
#include <cstdint>
#include <cstddef>

#define Bb 256
#define Tt 512
#define Ii 64
#define Hh 512
#define Gg 2048   // 4*H

// ---------------- tf32 mma.sync helpers (baseline PTX, sm_80+) -------------
__device__ __forceinline__ void mma_tf32(float* d, const uint32_t* a, const uint32_t* b) {
    asm volatile(
        "mma.sync.aligned.m16n8k8.row.col.f32.tf32.tf32.f32 "
        "{%0,%1,%2,%3}, {%4,%5,%6,%7}, {%8,%9}, {%0,%1,%2,%3};"
        : "+f"(d[0]), "+f"(d[1]), "+f"(d[2]), "+f"(d[3])
        : "r"(a[0]), "r"(a[1]), "r"(a[2]), "r"(a[3]), "r"(b[0]), "r"(b[1]));
}
__device__ __forceinline__ uint32_t f2tf32(float x) {
    uint32_t r; asm("cvt.rna.tf32.f32 %0, %1;" : "=r"(r) : "f"(x)); return r;
}
__device__ __forceinline__ float tf32f(float x) { return __uint_as_float(f2tf32(x)); }
__device__ __forceinline__ uint32_t fu(float x) { return __float_as_uint(x); }

__device__ __forceinline__ uint32_t smem_u32_of(const void* p) {
    uint32_t a;
    asm("{ .reg .u64 t; cvta.to.shared.u64 t, %1; cvt.u32.u64 %0, t; }" : "=r"(a) : "l"(p));
    return a;
}
__device__ __forceinline__ void cpa16(uint32_t dst, const void* src) {
    asm volatile("cp.async.cg.shared.global [%0], [%1], 16;"
                 :: "r"(dst), "l"(src) : "memory");
}
#define CP_COMMIT() asm volatile("cp.async.commit_group;" ::: "memory")
#define CP_WAIT0()  asm volatile("cp.async.wait_group 0;" ::: "memory")

// ---------------- static device scratch ------------------------------------
__device__ float g_xg[(size_t)Bb * Tt * Gg];     // 1.0 GiB gate pre-activations
__device__ float g_hseq[(size_t)Bb * Tt * Hh];   // 256 MiB layer-0 hidden seq
__device__ float g_hbuf[2 * (size_t)Bb * Hh];    // double-buffered h
__device__ unsigned int g_bar_count;             // grid barrier counter

__global__ void init_kernel() {
    unsigned idx = blockIdx.x * blockDim.x + threadIdx.x;
    if (idx < 2u * Bb * Hh) g_hbuf[idx] = 0.f;
    if (idx == 0) g_bar_count = 0u;
}

// ================= tf32 mma GEMM (validated, unchanged) =====================
#define GP 36
#define SA_BUF (128 * GP)
#define GEMM_SMEM_BYTES (4 * SA_BUF * 4)

__global__ void __launch_bounds__(256)
mma_gemm(const float* __restrict__ A, const float* __restrict__ W,
         const float* __restrict__ b1, const float* __restrict__ b2,
         float* __restrict__ C, int K)
{
    extern __shared__ float sm[];
    float* sA = sm;
    float* sB = sm + 2 * SA_BUF;

    const int tid = threadIdx.x;
    const int lane = tid & 31;
    const int wid = tid >> 5;
    const int gid = lane >> 2;
    const int tq = lane & 3;
    const int warpM = wid >> 2;
    const int warpN = wid & 3;
    const size_t n0 = (size_t)blockIdx.x * 128;
    const size_t m0 = (size_t)blockIdx.y * 128;
    const int NC = K >> 5;

    const int lrow = tid >> 3;
    const int lq = tid & 7;

    float acc[4][4][4];
#pragma unroll
    for (int mt = 0; mt < 4; ++mt)
#pragma unroll
        for (int nt = 0; nt < 4; ++nt)
#pragma unroll
            for (int k = 0; k < 4; ++k) acc[mt][nt][k] = 0.f;

    float4 pa[4], pb[4];
#pragma unroll
    for (int i = 0; i < 4; ++i) {
        int row = lrow + i * 32;
        pa[i] = *reinterpret_cast<const float4*>(&A[(m0 + row) * (size_t)K + lq * 4]);
        pb[i] = *reinterpret_cast<const float4*>(&W[(n0 + row) * (size_t)K + lq * 4]);
    }
#pragma unroll
    for (int i = 0; i < 4; ++i) {
        int row = lrow + i * 32;
        float* ap = &sA[row * GP + lq * 4];
        ap[0] = tf32f(pa[i].x); ap[1] = tf32f(pa[i].y); ap[2] = tf32f(pa[i].z); ap[3] = tf32f(pa[i].w);
        float* bp = &sB[row * GP + lq * 4];
        bp[0] = tf32f(pb[i].x); bp[1] = tf32f(pb[i].y); bp[2] = tf32f(pb[i].z); bp[3] = tf32f(pb[i].w);
    }
    __syncthreads();

#pragma unroll 1
    for (int c = 0; c < NC; ++c) {
        const int buf = c & 1;
        if (c + 1 < NC) {
            int k0 = (c + 1) * 32;
#pragma unroll
            for (int i = 0; i < 4; ++i) {
                int row = lrow + i * 32;
                pa[i] = *reinterpret_cast<const float4*>(&A[(m0 + row) * (size_t)K + k0 + lq * 4]);
                pb[i] = *reinterpret_cast<const float4*>(&W[(n0 + row) * (size_t)K + k0 + lq * 4]);
            }
        }
        const float* sAb = sA + buf * SA_BUF;
        const float* sBb = sB + buf * SA_BUF;
#pragma unroll
        for (int kk = 0; kk < 4; ++kk) {
            uint32_t a[4][4];
#pragma unroll
            for (int mt = 0; mt < 4; ++mt) {
                const float* ap = sAb + (warpM * 64 + mt * 16 + gid) * GP + kk * 8 + tq;
                a[mt][0] = fu(ap[0]);
                a[mt][1] = fu(ap[8 * GP]);
                a[mt][2] = fu(ap[4]);
                a[mt][3] = fu(ap[8 * GP + 4]);
            }
            uint32_t bf[4][2];
#pragma unroll
            for (int nt = 0; nt < 4; ++nt) {
                const float* bp = sBb + (warpN * 32 + nt * 8 + gid) * GP + kk * 8 + tq;
                bf[nt][0] = fu(bp[0]);
                bf[nt][1] = fu(bp[4]);
            }
#pragma unroll
            for (int mt = 0; mt < 4; ++mt)
#pragma unroll
                for (int nt = 0; nt < 4; ++nt)
                    mma_tf32(acc[mt][nt], a[mt], bf[nt]);
        }
        __syncthreads();
        if (c + 1 < NC) {
            float* dA = sA + (buf ^ 1) * SA_BUF;
            float* dB = sB + (buf ^ 1) * SA_BUF;
#pragma unroll
            for (int i = 0; i < 4; ++i) {
                int row = lrow + i * 32;
                float* ap = &dA[row * GP + lq * 4];
                ap[0] = tf32f(pa[i].x); ap[1] = tf32f(pa[i].y); ap[2] = tf32f(pa[i].z); ap[3] = tf32f(pa[i].w);
                float* bp = &dB[row * GP + lq * 4];
                bp[0] = tf32f(pb[i].x); bp[1] = tf32f(pb[i].y); bp[2] = tf32f(pb[i].z); bp[3] = tf32f(pb[i].w);
            }
            __syncthreads();
        }
    }

    float bias[4][2];
#pragma unroll
    for (int nt = 0; nt < 4; ++nt) {
        size_t ncol = n0 + warpN * 32 + nt * 8 + tq * 2;
        bias[nt][0] = b1[ncol] + b2[ncol];
        bias[nt][1] = b1[ncol + 1] + b2[ncol + 1];
    }
#pragma unroll
    for (int mt = 0; mt < 4; ++mt) {
        size_t r0 = m0 + warpM * 64 + mt * 16 + gid;
#pragma unroll
        for (int nt = 0; nt < 4; ++nt) {
            size_t ncol = n0 + warpN * 32 + nt * 8 + tq * 2;
            float2 v0, v1;
            v0.x = acc[mt][nt][0] + bias[nt][0];
            v0.y = acc[mt][nt][1] + bias[nt][1];
            v1.x = acc[mt][nt][2] + bias[nt][0];
            v1.y = acc[mt][nt][3] + bias[nt][1];
            *reinterpret_cast<float2*>(&C[r0 * Gg + ncol]) = v0;
            *reinterpret_cast<float2*>(&C[(r0 + 8) * Gg + ncol]) = v1;
        }
    }
}

// ================= persistent LSTM recurrence (cp.async staging) ============
// 128 CTAs = 4 M-tiles x 32 col-tiles. 8 warps = 2M x 2N x 2K-split.
// h and xg staged global->smem with cp.async.cg (L1 bypass => coherent, no
// STS crossbar cost, no cvt: mma consumes raw f32 as truncated tf32).
#define NCTA_R 128
#define RWP 516
#define RHP 132
#define SH_BUF (64 * RHP)
#define XGP 68
#define REC_SMEM_FLOATS (64 * RWP + 2 * SH_BUF + 64 * XGP)
#define REC_SMEM_BYTES (REC_SMEM_FLOATS * 4)

__device__ __forceinline__ float sigmoidf_(float x) {
    return 1.0f / (1.0f + __expf(-x));
}

__global__ void __launch_bounds__(256, 1)
lstm_rec(const float* __restrict__ W_hh, const float* __restrict__ xg,
         float* __restrict__ hseq)
{
    extern __shared__ float sm[];
    float* sW  = sm;                      // [64][516] tf32(rna)
    float* sH  = sm + 64 * RWP;           // 2 x [64][132] raw f32
    float* sXG = sH + 2 * SH_BUF;         // [64][68] raw f32
    float* sRed = sH;                     // alias h buffer 0

    const uint32_t sH_u  = smem_u32_of(sH);
    const uint32_t sXG_u = smem_u32_of(sXG);

    const int tid = threadIdx.x;
    const int lane = tid & 31;
    const int wid = tid >> 5;
    const int wK = wid >> 2;
    const int wM = (wid >> 1) & 1;
    const int wN = wid & 1;
    const int gid = lane >> 2;
    const int tq = lane & 3;
    const int p = lane & 1;

    const int ctaM = blockIdx.x & 3;
    const int ctaC = blockIdx.x >> 2;
    const int m0 = ctaM * 64;
    const int hc0 = ctaC * 16;

    // staging index decomposition (per thread)
    const int hr = tid >> 5;              // h: row-within-pass base (8 passes)
    const int hq = tid & 31;              // h: 16B column slot
    const int xr = tid >> 4;              // xg rows (4 passes)
    const int xq = tid & 15;

    // W_hh slice -> smem (tf32 rna), row j = cl*4 + g
    for (int idx = tid; idx < 64 * 512; idx += 256) {
        int j = idx >> 9, k = idx & 511;
        sW[j * RWP + k] = tf32f(W_hh[((size_t)(j & 3) * Hh + hc0 + (j >> 2)) * Hh + k]);
    }
    __syncthreads();

    float cst[8];
#pragma unroll
    for (int s = 0; s < 8; ++s) cst[s] = 0.f;
    unsigned phase = 0;

    // ---- xg(0) cp.async ----
#pragma unroll
    for (int it = 0; it < 4; ++it) {
        int row = xr + it * 16;
        cpa16(sXG_u + (row * XGP + xq * 4) * 4,
              &xg[((size_t)(m0 + row) * Tt + 0) * Gg + (size_t)(xq >> 2) * Hh + hc0 + (xq & 3) * 4]);
    }
    CP_COMMIT();

    for (int t = 0; t < Tt; ++t) {
        const float* hin = g_hbuf + (size_t)(t & 1) * Bb * Hh;
        float* hout = g_hbuf + (size_t)((t + 1) & 1) * Bb * Hh;

        // ---- h chunk 0 -> buf 0 via cp.async ----
#pragma unroll
        for (int it = 0; it < 8; ++it) {
            int r = hr + it * 8;
            cpa16(sH_u + (r * RHP + hq * 4) * 4,
                  &hin[(size_t)(m0 + r) * Hh + hq * 4]);
        }
        CP_COMMIT();
        CP_WAIT0();                        // drains xg group too
        __syncthreads();

        float acc[2][4][4];
#pragma unroll
        for (int mt = 0; mt < 2; ++mt)
#pragma unroll
            for (int nt = 0; nt < 4; ++nt)
#pragma unroll
                for (int k = 0; k < 4; ++k) acc[mt][nt][k] = 0.f;

        // ---- 4-chunk mainloop, one sync per chunk ----
#pragma unroll
        for (int cc = 0; cc < 4; ++cc) {
            if (cc < 3) {
                // issue chunk cc+1 into the other buffer (overlaps with mma)
                int kb = (cc + 1) * 128;
                uint32_t dstb = sH_u + ((cc + 1) & 1) * (SH_BUF * 4);
#pragma unroll
                for (int it = 0; it < 8; ++it) {
                    int r = hr + it * 8;
                    cpa16(dstb + (r * RHP + hq * 4) * 4,
                          &hin[(size_t)(m0 + r) * Hh + kb + hq * 4]);
                }
                CP_COMMIT();
            }
            const float* sHb = sH + (cc & 1) * SH_BUF;
            const int kq0 = wK * 64;
            const int wcol0 = cc * 128 + kq0;
#pragma unroll
            for (int kk = 0; kk < 8; ++kk) {
                uint32_t a[2][4];
#pragma unroll
                for (int mt = 0; mt < 2; ++mt) {
                    const float* ap = sHb + (wM * 32 + mt * 16 + gid) * RHP + kq0 + kk * 8 + tq;
                    a[mt][0] = fu(ap[0]);
                    a[mt][1] = fu(ap[8 * RHP]);
                    a[mt][2] = fu(ap[4]);
                    a[mt][3] = fu(ap[8 * RHP + 4]);
                }
#pragma unroll
                for (int nt = 0; nt < 4; ++nt) {
                    const float* bp = sW + (wN * 32 + nt * 8 + gid) * RWP + wcol0 + kk * 8 + tq;
                    uint32_t bfr[2];
                    bfr[0] = fu(bp[0]);
                    bfr[1] = fu(bp[4]);
#pragma unroll
                    for (int mt = 0; mt < 2; ++mt)
                        mma_tf32(acc[mt][nt], a[mt], bfr);
                }
            }
            if (cc == 3 && wK == 1) {
                // K-split partials -> sRed (aliases buf0; last read at cc=2)
                int pair = wM * 2 + wN;
#pragma unroll
                for (int mt = 0; mt < 2; ++mt)
#pragma unroll
                    for (int nt = 0; nt < 4; ++nt)
#pragma unroll
                        for (int r = 0; r < 4; ++r)
                            sRed[pair * 1024 + ((mt * 4 + nt) * 4 + r) * 32 + lane] = acc[mt][nt][r];
            }
            if (cc < 3) CP_WAIT0();
            __syncthreads();
        }

        if (wK == 0) {
            int pair = wM * 2 + wN;
#pragma unroll
            for (int mt = 0; mt < 2; ++mt)
#pragma unroll
                for (int nt = 0; nt < 4; ++nt)
#pragma unroll
                    for (int r = 0; r < 4; ++r)
                        acc[mt][nt][r] += sRed[pair * 1024 + ((mt * 4 + nt) * 4 + r) * 32 + lane];

            // ---- epilogue: gate exchange + cell update + h write ----
#pragma unroll
            for (int mt = 0; mt < 2; ++mt) {
                int rl = wM * 32 + mt * 16 + gid + p * 8;
                size_t grow = m0 + rl;
#pragma unroll
                for (int nt = 0; nt < 4; ++nt) {
                    float s0 = p ? acc[mt][nt][0] : acc[mt][nt][2];
                    float s1 = p ? acc[mt][nt][1] : acc[mt][nt][3];
                    float r0 = __shfl_xor_sync(0xffffffffu, s0, 1);
                    float r1 = __shfl_xor_sync(0xffffffffu, s1, 1);
                    float gi = p ? r0 : acc[mt][nt][0];
                    float gf = p ? r1 : acc[mt][nt][1];
                    float gg = p ? acc[mt][nt][2] : r0;
                    float go = p ? acc[mt][nt][3] : r1;
                    int cl = wN * 8 + nt * 2 + (tq >> 1);
                    const float* xp = &sXG[rl * XGP + cl];
                    float iv = sigmoidf_(gi + xp[0]);
                    float fv = sigmoidf_(gf + xp[16]);
                    float gv = tanhf(gg + xp[32]);
                    float ov = sigmoidf_(go + xp[48]);
                    int slot = mt * 4 + nt;
                    cst[slot] = fv * cst[slot] + iv * gv;
                    float hv = ov * tanhf(cst[slot]);
                    hout[grow * Hh + hc0 + cl] = hv;
                    if (hseq) hseq[(grow * Tt + t) * Hh + hc0 + cl] = hv;
                }
            }
        }

        // ---- pre-barrier sync (protects sXG), then xg(t+1) cp.async ----
        __syncthreads();
        if (t + 1 < Tt) {
#pragma unroll
            for (int it = 0; it < 4; ++it) {
                int row = xr + it * 16;
                cpa16(sXG_u + (row * XGP + xq * 4) * 4,
                      &xg[((size_t)(m0 + row) * Tt + (t + 1)) * Gg
                          + (size_t)(xq >> 2) * Hh + hc0 + (xq & 3) * 4]);
            }
            CP_COMMIT();
        }

        // ---- grid barrier: release arrive + acquire spin ----
        phase += NCTA_R;
        if (tid == 0) {
            asm volatile("red.release.gpu.add.u32 [%0], %1;"
                         :: "l"(&g_bar_count), "r"(1u) : "memory");
            unsigned v;
            while (true) {
                asm volatile("ld.acquire.gpu.u32 %0, [%1];"
                             : "=r"(v) : "l"(&g_bar_count) : "memory");
                if (v >= phase) break;
                __nanosleep(32);
            }
        }
        __syncthreads();
    }
}

// ---------------- final FC --------------------------------------------------
__global__ void fc_kernel(const float* __restrict__ h, const float* __restrict__ Wfc,
                          const float* __restrict__ bfc, float* __restrict__ out)
{
    int b = blockIdx.x;
    int tid = threadIdx.x;
    float s = 0.f;
    for (int k = tid; k < Hh; k += 128)
        s += h[(size_t)b * Hh + k] * Wfc[k];
#pragma unroll
    for (int o = 16; o > 0; o >>= 1) s += __shfl_xor_sync(0xffffffffu, s, o);
    __shared__ float ws[4];
    if ((tid & 31) == 0) ws[tid >> 5] = s;
    __syncthreads();
    if (tid == 0) out[b] = ws[0] + ws[1] + ws[2] + ws[3] + bfc[0];
}

// ---------------- launch ----------------------------------------------------
extern "C" void kernel_launch(void* const* d_in, const int* in_sizes, int n_in,
                              void* d_out, int out_size)
{
    (void)in_sizes; (void)n_in; (void)out_size;
    const float* x     = (const float*)d_in[0];
    const float* W_ih0 = (const float*)d_in[1];
    const float* W_hh0 = (const float*)d_in[2];
    const float* b_ih0 = (const float*)d_in[3];
    const float* b_hh0 = (const float*)d_in[4];
    const float* W_ih1 = (const float*)d_in[5];
    const float* W_hh1 = (const float*)d_in[6];
    const float* b_ih1 = (const float*)d_in[7];
    const float* b_hh1 = (const float*)d_in[8];
    const float* W_fc  = (const float*)d_in[9];
    const float* b_fc  = (const float*)d_in[10];
    float* out = (float*)d_out;

    void *p_xg = nullptr, *p_hseq = nullptr, *p_hbuf = nullptr;
    cudaGetSymbolAddress(&p_xg, g_xg);
    cudaGetSymbolAddress(&p_hseq, g_hseq);
    cudaGetSymbolAddress(&p_hbuf, g_hbuf);

    cudaFuncSetAttribute(mma_gemm, cudaFuncAttributeMaxDynamicSharedMemorySize,
                         GEMM_SMEM_BYTES);
    cudaFuncSetAttribute(lstm_rec, cudaFuncAttributeMaxDynamicSharedMemorySize,
                         REC_SMEM_BYTES);

    dim3 ggrid(Gg / 128, (Bb * Tt) / 128);   // (16, 1024)

    // Layer 0
    mma_gemm<<<ggrid, 256, GEMM_SMEM_BYTES>>>(x, W_ih0, b_ih0, b_hh0, (float*)p_xg, Ii);
    init_kernel<<<1024, 256>>>();
    lstm_rec<<<NCTA_R, 256, REC_SMEM_BYTES>>>(W_hh0, (const float*)p_xg, (float*)p_hseq);

    // Layer 1
    mma_gemm<<<ggrid, 256, GEMM_SMEM_BYTES>>>((const float*)p_hseq, W_ih1, b_ih1, b_hh1,
                                              (float*)p_xg, Hh);
    init_kernel<<<1024, 256>>>();
    lstm_rec<<<NCTA_R, 256, REC_SMEM_BYTES>>>(W_hh1, (const float*)p_xg, nullptr);

    // Final FC (h_last ends in buffer 0 since T=512 is even)
    fc_kernel<<<Bb, 128>>>((const float*)p_hbuf, W_fc, b_fc, out);
}